// round 1
// baseline (speedup 1.0000x reference)
#include <cuda_runtime.h>

// Problem constants
#define HDIM   1024
#define SEQ    2048
#define BATCH  2
#define NHEADS 16
#define HEADD  64

// Scratch (allocation-free rule: __device__ globals)
__device__ float g_q [BATCH*NHEADS*SEQ*HEADD];
__device__ float g_k [BATCH*NHEADS*SEQ*HEADD];
__device__ float g_v [BATCH*NHEADS*SEQ*HEADD];
__device__ float g_ao[BATCH*SEQ*HDIM];

// ---------------------------------------------------------------------------
// GEMM: out[m,n] = sum_k A[m,k] * W[n,k]   (A: [4096,1024], W: [1024,1024])
// dst_mode: 1/2/3 -> write g_q/g_k/g_v in [b,h,s,d] layout (A = A_in)
//           0     -> write Cout row-major [m,1024]        (A = g_ao)
// Tile 64x64x16, 256 threads, 4x4 microtile.
// ---------------------------------------------------------------------------
__global__ __launch_bounds__(256) void gemm_kernel(
    const float* __restrict__ A_in, const float* __restrict__ W,
    float* __restrict__ Cout, int dst_mode)
{
    __shared__ __align__(16) float As[64 * 16];   // [m][k] natural
    __shared__ __align__(16) float Ws[16 * 68];   // [k][n] transposed, pad 68

    const float* A = (dst_mode == 0) ? g_ao : A_in;

    const int m0 = blockIdx.y * 64;
    const int n0 = blockIdx.x * 64;
    const int t  = threadIdx.x;
    const int tx = t & 15;
    const int ty = t >> 4;
    const int lr = t >> 2;            // 0..63 (row within tile)
    const int lk = (t & 3) << 2;      // 0,4,8,12 (k offset)

    float c[4][4] = {{0.f,0.f,0.f,0.f},{0.f,0.f,0.f,0.f},
                     {0.f,0.f,0.f,0.f},{0.f,0.f,0.f,0.f}};

    for (int k0 = 0; k0 < HDIM; k0 += 16) {
        float4 av = *(const float4*)(A + (size_t)(m0 + lr) * HDIM + k0 + lk);
        float4 wv = *(const float4*)(W + (size_t)(n0 + lr) * HDIM + k0 + lk);
        __syncthreads();
        *(float4*)(As + lr * 16 + lk) = av;
        Ws[(lk + 0) * 68 + lr] = wv.x;
        Ws[(lk + 1) * 68 + lr] = wv.y;
        Ws[(lk + 2) * 68 + lr] = wv.z;
        Ws[(lk + 3) * 68 + lr] = wv.w;
        __syncthreads();

        #pragma unroll
        for (int kk = 0; kk < 16; kk++) {
            float a0 = As[(ty * 4 + 0) * 16 + kk];
            float a1 = As[(ty * 4 + 1) * 16 + kk];
            float a2 = As[(ty * 4 + 2) * 16 + kk];
            float a3 = As[(ty * 4 + 3) * 16 + kk];
            float4 bv = *(const float4*)(Ws + kk * 68 + tx * 4);
            c[0][0] += a0 * bv.x; c[0][1] += a0 * bv.y; c[0][2] += a0 * bv.z; c[0][3] += a0 * bv.w;
            c[1][0] += a1 * bv.x; c[1][1] += a1 * bv.y; c[1][2] += a1 * bv.z; c[1][3] += a1 * bv.w;
            c[2][0] += a2 * bv.x; c[2][1] += a2 * bv.y; c[2][2] += a2 * bv.z; c[2][3] += a2 * bv.w;
            c[3][0] += a3 * bv.x; c[3][1] += a3 * bv.y; c[3][2] += a3 * bv.z; c[3][3] += a3 * bv.w;
        }
    }

    if (dst_mode == 0) {
        #pragma unroll
        for (int i = 0; i < 4; i++) {
            int m = m0 + ty * 4 + i;
            *(float4*)(Cout + (size_t)m * HDIM + n0 + tx * 4) =
                make_float4(c[i][0], c[i][1], c[i][2], c[i][3]);
        }
    } else {
        float* dst = (dst_mode == 1) ? g_q : (dst_mode == 2) ? g_k : g_v;
        int n = n0 + tx * 4;
        int h = n >> 6, d = n & 63;
        #pragma unroll
        for (int i = 0; i < 4; i++) {
            int m = m0 + ty * 4 + i;
            int b = m >> 11, s = m & (SEQ - 1);
            size_t off = (((size_t)(b * NHEADS + h) * SEQ + s) * HEADD + d);
            *(float4*)(dst + off) = make_float4(c[i][0], c[i][1], c[i][2], c[i][3]);
        }
    }
}

// ---------------------------------------------------------------------------
// RoPE in-place on g_q, g_k. One thread per (bh, s, d<32) pair.
// d<32:  out_d      = x_d*cos[d]   - x_{d+32}*sin[d]
// d>=32: out_{d+32} = x_{d+32}*cos[d] + x_d*sin[d]
// ---------------------------------------------------------------------------
__global__ __launch_bounds__(256) void rope_kernel(
    const float* __restrict__ rc, const float* __restrict__ rs)
{
    int idx = blockIdx.x * blockDim.x + threadIdx.x;   // [0, B*NH*S*32)
    int d  = idx & 31;
    int s  = (idx >> 5) & (SEQ - 1);
    int bh = idx >> 16;                                // 32 * 2048 = 65536 per bh
    size_t base = ((size_t)bh * SEQ + s) * HEADD;
    float cc = rc[s * 32 + d];
    float ss = rs[s * 32 + d];

    float q1 = g_q[base + d], q2 = g_q[base + d + 32];
    g_q[base + d]      = q1 * cc - q2 * ss;
    g_q[base + d + 32] = q2 * cc + q1 * ss;

    float k1 = g_k[base + d], k2 = g_k[base + d + 32];
    g_k[base + d]      = k1 * cc - k2 * ss;
    g_k[base + d + 32] = k2 * cc + k1 * ss;
}

// ---------------------------------------------------------------------------
// Flash attention: block = (b,h, q-tile of 64 rows). 256 threads.
// Smem: Qs[64][64] (q pre-scaled by 1/8), Ks[64][68] d-major, Vs[64][64],
//       Ps[64][64]. Online softmax with per-row (m,l) in registers,
//       row owned by a 16-lane group (shfl-xor reductions, width 16).
// ---------------------------------------------------------------------------
#define ATTN_SMEM_FLOATS (64*64 + 64*68 + 64*64 + 64*64)   // 16640
#define ATTN_SMEM_BYTES  (ATTN_SMEM_FLOATS * 4)            // 66560

__global__ __launch_bounds__(256) void attn_kernel()
{
    extern __shared__ float sm[];
    float* Qs = sm;                    // 4096 floats [r][d]
    float* Ks = sm + 4096;             // 4352 floats [d][c] pad 68
    float* Vs = sm + 4096 + 4352;      // 4096 floats [c][d]
    float* Ps = Vs + 4096;             // 4096 floats [r][c]

    const int bh = blockIdx.y;         // 0..31
    const int qi = blockIdx.x;         // 0..31
    const int t  = threadIdx.x;
    const int tx = t & 15;
    const int ty = t >> 4;

    const float* qp = g_q + ((size_t)bh * SEQ + qi * 64) * HEADD;
    #pragma unroll
    for (int it = 0; it < 4; it++) {
        float4 qv = ((const float4*)qp)[t + it * 256];
        qv.x *= 0.125f; qv.y *= 0.125f; qv.z *= 0.125f; qv.w *= 0.125f;  // fold scale
        ((float4*)Qs)[t + it * 256] = qv;
    }

    float m_i[4], l_i[4], acc[4][4];
    #pragma unroll
    for (int i = 0; i < 4; i++) {
        m_i[i] = -1e30f; l_i[i] = 0.f;
        acc[i][0] = acc[i][1] = acc[i][2] = acc[i][3] = 0.f;
    }

    for (int kt = 0; kt < SEQ / 64; kt++) {
        const float* kp = g_k + ((size_t)bh * SEQ + kt * 64) * HEADD;
        const float* vp = g_v + ((size_t)bh * SEQ + kt * 64) * HEADD;

        __syncthreads();                       // prior PV reads of Ks/Vs done
        #pragma unroll
        for (int it = 0; it < 16; it++) {
            int e = t + it * 256;
            Ks[(e & 63) * 68 + (e >> 6)] = kp[e];      // transpose to [d][c]
        }
        #pragma unroll
        for (int it = 0; it < 4; it++)
            ((float4*)Vs)[t + it * 256] = ((const float4*)vp)[t + it * 256];
        __syncthreads();

        // S = Qs * Ks  (scores, 64x64)
        float sc[4][4] = {{0.f,0.f,0.f,0.f},{0.f,0.f,0.f,0.f},
                          {0.f,0.f,0.f,0.f},{0.f,0.f,0.f,0.f}};
        #pragma unroll
        for (int d = 0; d < 64; d++) {
            float4 bv = *(const float4*)(Ks + d * 68 + tx * 4);
            float a0 = Qs[(ty * 4 + 0) * 64 + d];
            float a1 = Qs[(ty * 4 + 1) * 64 + d];
            float a2 = Qs[(ty * 4 + 2) * 64 + d];
            float a3 = Qs[(ty * 4 + 3) * 64 + d];
            sc[0][0] += a0 * bv.x; sc[0][1] += a0 * bv.y; sc[0][2] += a0 * bv.z; sc[0][3] += a0 * bv.w;
            sc[1][0] += a1 * bv.x; sc[1][1] += a1 * bv.y; sc[1][2] += a1 * bv.z; sc[1][3] += a1 * bv.w;
            sc[2][0] += a2 * bv.x; sc[2][1] += a2 * bv.y; sc[2][2] += a2 * bv.z; sc[2][3] += a2 * bv.w;
            sc[3][0] += a3 * bv.x; sc[3][1] += a3 * bv.y; sc[3][2] += a3 * bv.z; sc[3][3] += a3 * bv.w;
        }

        // Online softmax per row (rows ty*4+i owned by the 16-lane tx group)
        #pragma unroll
        for (int i = 0; i < 4; i++) {
            float rm = fmaxf(fmaxf(sc[i][0], sc[i][1]), fmaxf(sc[i][2], sc[i][3]));
            #pragma unroll
            for (int off = 8; off > 0; off >>= 1)
                rm = fmaxf(rm, __shfl_xor_sync(0xffffffffu, rm, off, 16));
            float mn = fmaxf(m_i[i], rm);
            float al = __expf(m_i[i] - mn);
            m_i[i] = mn;
            float rsum = 0.f;
            #pragma unroll
            for (int j = 0; j < 4; j++) {
                sc[i][j] = __expf(sc[i][j] - mn);
                rsum += sc[i][j];
            }
            #pragma unroll
            for (int off = 8; off > 0; off >>= 1)
                rsum += __shfl_xor_sync(0xffffffffu, rsum, off, 16);
            l_i[i] = l_i[i] * al + rsum;
            acc[i][0] *= al; acc[i][1] *= al; acc[i][2] *= al; acc[i][3] *= al;
            *(float4*)(Ps + (ty * 4 + i) * 64 + tx * 4) =
                make_float4(sc[i][0], sc[i][1], sc[i][2], sc[i][3]);
        }
        __syncthreads();

        // O += P * V
        #pragma unroll
        for (int cc = 0; cc < 64; cc++) {
            float4 bv = *(const float4*)(Vs + cc * 64 + tx * 4);
            float a0 = Ps[(ty * 4 + 0) * 64 + cc];
            float a1 = Ps[(ty * 4 + 1) * 64 + cc];
            float a2 = Ps[(ty * 4 + 2) * 64 + cc];
            float a3 = Ps[(ty * 4 + 3) * 64 + cc];
            acc[0][0] += a0 * bv.x; acc[0][1] += a0 * bv.y; acc[0][2] += a0 * bv.z; acc[0][3] += a0 * bv.w;
            acc[1][0] += a1 * bv.x; acc[1][1] += a1 * bv.y; acc[1][2] += a1 * bv.z; acc[1][3] += a1 * bv.w;
            acc[2][0] += a2 * bv.x; acc[2][1] += a2 * bv.y; acc[2][2] += a2 * bv.z; acc[2][3] += a2 * bv.w;
            acc[3][0] += a3 * bv.x; acc[3][1] += a3 * bv.y; acc[3][2] += a3 * bv.z; acc[3][3] += a3 * bv.w;
        }
    }

    // Epilogue: normalize and write to g_ao in [B, S, H] layout
    const int b = bh >> 4;
    const int h = bh & 15;
    #pragma unroll
    for (int i = 0; i < 4; i++) {
        int s_ = qi * 64 + ty * 4 + i;
        float inv = 1.0f / l_i[i];
        float4 o = make_float4(acc[i][0] * inv, acc[i][1] * inv,
                               acc[i][2] * inv, acc[i][3] * inv);
        *(float4*)(g_ao + ((size_t)(b * SEQ + s_)) * HDIM + h * HEADD + tx * 4) = o;
    }
}

// ---------------------------------------------------------------------------
extern "C" void kernel_launch(void* const* d_in, const int* in_sizes, int n_in,
                              void* d_out, int out_size)
{
    const float* x  = (const float*)d_in[0];
    const float* Wq = (const float*)d_in[1];
    const float* Wk = (const float*)d_in[2];
    const float* Wv = (const float*)d_in[3];
    const float* Wo = (const float*)d_in[4];
    const float* rc = (const float*)d_in[5];
    const float* rs = (const float*)d_in[6];
    float* out = (float*)d_out;

    cudaFuncSetAttribute(attn_kernel,
                         cudaFuncAttributeMaxDynamicSharedMemorySize,
                         ATTN_SMEM_BYTES);

    dim3 ggrid(HDIM / 64, (BATCH * SEQ) / 64);   // (16, 64)
    gemm_kernel<<<ggrid, 256>>>(x, Wq, nullptr, 1);
    gemm_kernel<<<ggrid, 256>>>(x, Wk, nullptr, 2);
    gemm_kernel<<<ggrid, 256>>>(x, Wv, nullptr, 3);

    rope_kernel<<<(BATCH * NHEADS * SEQ * 32) / 256, 256>>>(rc, rs);

    attn_kernel<<<dim3(SEQ / 64, BATCH * NHEADS), 256, ATTN_SMEM_BYTES>>>();

    gemm_kernel<<<ggrid, 256>>>(nullptr, Wo, out, 0);
}

// round 2
// speedup vs baseline: 2.5430x; 2.5430x over previous
#include <cuda_runtime.h>
#include <cstdint>

#define HDIM   1024
#define SEQ    2048
#define BATCH  2
#define NHEADS 16
#define HEADD  64

// Scratch (__device__ globals; no allocations allowed)
__device__ float g_q [BATCH*NHEADS*SEQ*HEADD];
__device__ float g_k [BATCH*NHEADS*SEQ*HEADD];
__device__ float g_v [BATCH*NHEADS*SEQ*HEADD];
__device__ float g_ao[BATCH*SEQ*HDIM];

// ---------------------------------------------------------------- helpers
__device__ __forceinline__ float f2tf(float x) {            // round-to-nearest tf32
    unsigned u; asm("cvt.rna.tf32.f32 %0,%1;" : "=r"(u) : "f"(x));
    return __uint_as_float(u);
}
__device__ __forceinline__ float ex2f(float x) {
    float r; asm("ex2.approx.f32 %0,%1;" : "=f"(r) : "f"(x)); return r;
}
__device__ __forceinline__ unsigned sptr(const void* p) {
    return (unsigned)__cvta_generic_to_shared(p);
}
__device__ __forceinline__ void ldsm4(unsigned a[4], unsigned addr) {
    asm volatile("ldmatrix.sync.aligned.m8n8.x4.shared.b16 {%0,%1,%2,%3}, [%4];"
        : "=r"(a[0]), "=r"(a[1]), "=r"(a[2]), "=r"(a[3]) : "r"(addr));
}
__device__ __forceinline__ void mma8(float c[4], const unsigned a[4], const unsigned b[2]) {
    asm volatile(
        "mma.sync.aligned.m16n8k8.row.col.f32.tf32.tf32.f32 "
        "{%0,%1,%2,%3}, {%4,%5,%6,%7}, {%8,%9}, {%0,%1,%2,%3};\n"
        : "+f"(c[0]), "+f"(c[1]), "+f"(c[2]), "+f"(c[3])
        : "r"(a[0]), "r"(a[1]), "r"(a[2]), "r"(a[3]), "r"(b[0]), "r"(b[1]));
}
__device__ __forceinline__ void st8(float* d, float4 a, float4 b) {
    d[0]=f2tf(a.x); d[1]=f2tf(a.y); d[2]=f2tf(a.z); d[3]=f2tf(a.w);
    d[4]=f2tf(b.x); d[5]=f2tf(b.y); d[6]=f2tf(b.z); d[7]=f2tf(b.w);
}

// ---------------------------------------------------------------------------
// Tensor-core GEMM: C[m,n] = sum_k A[m,k] * W[n,k]
// Block 128x128, 8 warps (2x4 -> 64x32 warp tiles), K-step 16, double buffer.
// smem rows padded to 20 floats (80B stride => conflict-free ldmatrix).
// dst_mode: 1/2/3 scatter into g_q/g_k/g_v in [b,h,s,d]; 0 -> Cout row-major.
// ---------------------------------------------------------------------------
__global__ __launch_bounds__(256) void gemm_tc(
    const float* __restrict__ A_in, const float* __restrict__ W,
    float* __restrict__ Cout, int dst_mode)
{
    __shared__ __align__(16) float As[2][128*20];
    __shared__ __align__(16) float Bs[2][128*20];

    const float* A = (dst_mode == 0) ? g_ao : A_in;
    const int m0 = blockIdx.y * 128, n0 = blockIdx.x * 128;
    const int t = threadIdx.x, lane = t & 31, wid = t >> 5;
    const int wm = (wid & 1) * 64, wn = (wid >> 1) * 32;

    // global -> smem staging: each thread owns 8 contiguous floats of one row
    const int grow = t >> 1;
    const int gcol = (t & 1) * 8;
    const float* Ag = A + (size_t)(m0 + grow) * HDIM + gcol;
    const float* Bg = W + (size_t)(n0 + grow) * HDIM + gcol;
    const int sst = grow * 20 + gcol;

    // ldmatrix base addresses (lane s = sub-matrix id, r = row-in-sub)
    const int s = lane >> 3, r = lane & 7;
    const unsigned aAddr = sptr(&As[0][(wm + (s & 1) * 8 + r) * 20 + (s >> 1) * 4]);
    const unsigned bAddr = sptr(&Bs[0][(wn + (s >> 1) * 8 + r) * 20 + (s & 1) * 4]);

    float c[4][4][4];
    #pragma unroll
    for (int i = 0; i < 4; i++)
        #pragma unroll
        for (int j = 0; j < 4; j++)
            #pragma unroll
            for (int q = 0; q < 4; q++) c[i][j][q] = 0.f;

    float4 ra0 = *(const float4*)(Ag);
    float4 ra1 = *(const float4*)(Ag + 4);
    float4 rb0 = *(const float4*)(Bg);
    float4 rb1 = *(const float4*)(Bg + 4);
    st8(&As[0][sst], ra0, ra1);
    st8(&Bs[0][sst], rb0, rb1);
    __syncthreads();

    const int NIT = HDIM / 16;
    for (int it = 0; it < NIT; it++) {
        const int buf = it & 1;
        const bool pre = (it + 1 < NIT);
        if (pre) {
            const float* Ap = Ag + (it + 1) * 16;
            const float* Bp = Bg + (it + 1) * 16;
            ra0 = *(const float4*)(Ap);     ra1 = *(const float4*)(Ap + 4);
            rb0 = *(const float4*)(Bp);     rb1 = *(const float4*)(Bp + 4);
        }
        const unsigned bo = buf * (128 * 20 * 4);
        #pragma unroll
        for (int kc = 0; kc < 16; kc += 8) {
            unsigned aa[4][4], bb[2][4];
            #pragma unroll
            for (int mt = 0; mt < 4; mt++) ldsm4(aa[mt], aAddr + bo + mt * 1280 + kc * 4);
            #pragma unroll
            for (int p = 0; p < 2; p++)    ldsm4(bb[p], bAddr + bo + p * 1280 + kc * 4);
            #pragma unroll
            for (int mt = 0; mt < 4; mt++)
                #pragma unroll
                for (int nt = 0; nt < 4; nt++)
                    mma8(c[mt][nt], aa[mt], &bb[nt >> 1][(nt & 1) * 2]);
        }
        if (pre) {
            st8(&As[buf ^ 1][sst], ra0, ra1);
            st8(&Bs[buf ^ 1][sst], rb0, rb1);
        }
        __syncthreads();
    }

    // epilogue
    const int grp = lane >> 2, tig = lane & 3;
    if (dst_mode == 0) {
        #pragma unroll
        for (int mt = 0; mt < 4; mt++)
            #pragma unroll
            for (int nt = 0; nt < 4; nt++) {
                int m = m0 + wm + mt * 16 + grp;
                int n = n0 + wn + nt * 8 + tig * 2;
                *(float2*)(Cout + (size_t)m * HDIM + n)       = make_float2(c[mt][nt][0], c[mt][nt][1]);
                *(float2*)(Cout + (size_t)(m + 8) * HDIM + n) = make_float2(c[mt][nt][2], c[mt][nt][3]);
            }
    } else {
        float* dst = (dst_mode == 1) ? g_q : (dst_mode == 2) ? g_k : g_v;
        #pragma unroll
        for (int mt = 0; mt < 4; mt++)
            #pragma unroll
            for (int nt = 0; nt < 4; nt++) {
                int m = m0 + wm + mt * 16 + grp;
                int n = n0 + wn + nt * 8 + tig * 2;
                int h = n >> 6, d = n & 63;
                int b = m >> 11, sq = m & (SEQ - 1);
                size_t off = (((size_t)(b * NHEADS + h) * SEQ) + sq) * HEADD + d;
                *(float2*)(dst + off)             = make_float2(c[mt][nt][0], c[mt][nt][1]);
                *(float2*)(dst + off + 8 * HEADD) = make_float2(c[mt][nt][2], c[mt][nt][3]);
            }
    }
}

// ---------------------------------------------------------------------------
// RoPE in-place on g_q, g_k (unchanged from R1 — 14us, not worth touching yet)
// ---------------------------------------------------------------------------
__global__ __launch_bounds__(256) void rope_kernel(
    const float* __restrict__ rc, const float* __restrict__ rs)
{
    int idx = blockIdx.x * blockDim.x + threadIdx.x;
    int d  = idx & 31;
    int sq = (idx >> 5) & (SEQ - 1);
    int bh = idx >> 16;
    size_t base = ((size_t)bh * SEQ + sq) * HEADD;
    float cc = rc[sq * 32 + d];
    float ss = rs[sq * 32 + d];

    float q1 = g_q[base + d], q2 = g_q[base + d + 32];
    g_q[base + d]      = q1 * cc - q2 * ss;
    g_q[base + d + 32] = q2 * cc + q1 * ss;

    float k1 = g_k[base + d], k2 = g_k[base + d + 32];
    g_k[base + d]      = k1 * cc - k2 * ss;
    g_k[base + d + 32] = k2 * cc + k1 * ss;
}

// ---------------------------------------------------------------------------
// Flash attention, tensor cores. Block = (q-tile 128, bh). 256 thr, 8 warps.
// Each warp owns a 16-row band (softmax stays within 4-lane groups).
// smem: Ks[64][68], Vt[64][68] (V transposed), Ps[128][68] (Q stage + P).
// Q pre-scaled by 0.125*log2e, softmax in base-2 via ex2.approx.
// ---------------------------------------------------------------------------
#define ATT_SMEM ((64*68 + 64*68 + 128*68) * 4)   // 69632 B

__global__ __launch_bounds__(256) void attn_tc()
{
    extern __shared__ __align__(16) float smf[];
    float* Ks = smf;
    float* Vt = smf + 64 * 68;
    float* Ps = smf + 2 * 64 * 68;

    const int bh = blockIdx.y, qt = blockIdx.x;
    const int t = threadIdx.x, lane = t & 31, wid = t >> 5;
    const int s = lane >> 3, r = lane & 7;
    const int grp = lane >> 2, tig = lane & 3;

    // ---- stage Q (scaled) through Ps and capture register fragments
    const float* qp = g_q + ((size_t)bh * SEQ + qt * 128) * HEADD;
    const float QS = 0.125f * 1.4426950408889634f;   // scale * log2(e)
    #pragma unroll
    for (int it = 0; it < 8; it++) {
        int i = t + it * 256;
        int row = i >> 4, c4 = (i & 15) * 4;
        float4 v = *(const float4*)(qp + row * 64 + c4);
        float* d = Ps + row * 68 + c4;
        d[0] = f2tf(v.x * QS); d[1] = f2tf(v.y * QS);
        d[2] = f2tf(v.z * QS); d[3] = f2tf(v.w * QS);
    }
    __syncthreads();

    const unsigned qAddr = sptr(Ps) + ((wid * 16 + (s & 1) * 8 + r) * 68 + (s >> 1) * 4) * 4;
    unsigned qf[8][4];
    #pragma unroll
    for (int kc = 0; kc < 8; kc++) ldsm4(qf[kc], qAddr + kc * 32);

    const unsigned kAddr = sptr(Ks) + (((s >> 1) * 8 + r) * 68 + (s & 1) * 4) * 4;
    const unsigned vAddr = sptr(Vt) + (((s >> 1) * 8 + r) * 68 + (s & 1) * 4) * 4;
    const unsigned pAddr = qAddr;   // same formula, Ps base

    float o[8][4];
    #pragma unroll
    for (int nt = 0; nt < 8; nt++)
        { o[nt][0] = o[nt][1] = o[nt][2] = o[nt][3] = 0.f; }
    float m_u = -1e30f, m_d = -1e30f, l_u = 0.f, l_d = 0.f;

    const float* kbase = g_k + (size_t)bh * SEQ * HEADD;
    const float* vbase = g_v + (size_t)bh * SEQ * HEADD;

    for (int kt = 0; kt < SEQ / 64; kt++) {
        __syncthreads();                       // prev iter's MMA reads done
        const float* kp = kbase + kt * 64 * HEADD;
        const float* vp = vbase + kt * 64 * HEADD;
        #pragma unroll
        for (int it = 0; it < 4; it++) {
            int i = t + it * 256;
            int row = i >> 4, c4 = (i & 15) * 4;
            float4 kv = *(const float4*)(kp + row * 64 + c4);
            float* d = Ks + row * 68 + c4;
            d[0] = f2tf(kv.x); d[1] = f2tf(kv.y); d[2] = f2tf(kv.z); d[3] = f2tf(kv.w);
            float4 vv = *(const float4*)(vp + row * 64 + c4);
            Vt[(c4 + 0) * 68 + row] = f2tf(vv.x);
            Vt[(c4 + 1) * 68 + row] = f2tf(vv.y);
            Vt[(c4 + 2) * 68 + row] = f2tf(vv.z);
            Vt[(c4 + 3) * 68 + row] = f2tf(vv.w);
        }
        __syncthreads();

        // ---- S = Q K^T (warp: 16 x 64)
        float sc[8][4];
        #pragma unroll
        for (int nt = 0; nt < 8; nt++)
            { sc[nt][0] = sc[nt][1] = sc[nt][2] = sc[nt][3] = 0.f; }
        #pragma unroll
        for (int kc = 0; kc < 8; kc++) {
            unsigned kb[4][4];
            #pragma unroll
            for (int p = 0; p < 4; p++) ldsm4(kb[p], kAddr + p * (16*68*4) + kc * 32);
            #pragma unroll
            for (int nt = 0; nt < 8; nt++)
                mma8(sc[nt], qf[kc], &kb[nt >> 1][(nt & 1) * 2]);
        }

        // ---- online softmax (rows grp and grp+8; reduce across 4 lanes)
        float mu = -1e30f, md = -1e30f;
        #pragma unroll
        for (int nt = 0; nt < 8; nt++) {
            mu = fmaxf(mu, fmaxf(sc[nt][0], sc[nt][1]));
            md = fmaxf(md, fmaxf(sc[nt][2], sc[nt][3]));
        }
        mu = fmaxf(mu, __shfl_xor_sync(0xffffffffu, mu, 1));
        mu = fmaxf(mu, __shfl_xor_sync(0xffffffffu, mu, 2));
        md = fmaxf(md, __shfl_xor_sync(0xffffffffu, md, 1));
        md = fmaxf(md, __shfl_xor_sync(0xffffffffu, md, 2));
        float mnu = fmaxf(m_u, mu), mnd = fmaxf(m_d, md);
        float au = ex2f(m_u - mnu), ad = ex2f(m_d - mnd);
        m_u = mnu; m_d = mnd;

        float su = 0.f, sd = 0.f;
        #pragma unroll
        for (int nt = 0; nt < 8; nt++) {
            float p0 = ex2f(sc[nt][0] - mnu), p1 = ex2f(sc[nt][1] - mnu);
            float p2 = ex2f(sc[nt][2] - mnd), p3 = ex2f(sc[nt][3] - mnd);
            su += p0 + p1; sd += p2 + p3;
            float* pr = Ps + (wid * 16 + grp) * 68 + nt * 8 + tig * 2;
            *(float2*)pr            = make_float2(f2tf(p0), f2tf(p1));
            *(float2*)(pr + 8 * 68) = make_float2(f2tf(p2), f2tf(p3));
        }
        su += __shfl_xor_sync(0xffffffffu, su, 1);
        su += __shfl_xor_sync(0xffffffffu, su, 2);
        sd += __shfl_xor_sync(0xffffffffu, sd, 1);
        sd += __shfl_xor_sync(0xffffffffu, sd, 2);
        l_u = l_u * au + su;
        l_d = l_d * ad + sd;
        #pragma unroll
        for (int nt = 0; nt < 8; nt++) {
            o[nt][0] *= au; o[nt][1] *= au;
            o[nt][2] *= ad; o[nt][3] *= ad;
        }
        __syncthreads();                        // P visible to all warps

        // ---- O += P V   (warp: 16 x 64, k = 64)
        #pragma unroll
        for (int kc = 0; kc < 8; kc++) {
            unsigned pa[4];
            ldsm4(pa, pAddr + kc * 32);
            unsigned vb[4][4];
            #pragma unroll
            for (int p = 0; p < 4; p++) ldsm4(vb[p], vAddr + p * (16*68*4) + kc * 32);
            #pragma unroll
            for (int nt = 0; nt < 8; nt++)
                mma8(o[nt], pa, &vb[nt >> 1][(nt & 1) * 2]);
        }
    }

    // ---- epilogue: normalize, write g_ao [B,S,H]
    const int b = bh >> 4, h = bh & 15;
    const float iu = 1.f / l_u, id = 1.f / l_d;
    const int srow = qt * 128 + wid * 16 + grp;
    float* obase = g_ao + ((size_t)(b * SEQ + srow)) * HDIM + h * HEADD;
    #pragma unroll
    for (int nt = 0; nt < 8; nt++) {
        int d = nt * 8 + tig * 2;
        *(float2*)(obase + d)            = make_float2(o[nt][0] * iu, o[nt][1] * iu);
        *(float2*)(obase + 8 * HDIM + d) = make_float2(o[nt][2] * id, o[nt][3] * id);
    }
}

// ---------------------------------------------------------------------------
extern "C" void kernel_launch(void* const* d_in, const int* in_sizes, int n_in,
                              void* d_out, int out_size)
{
    const float* x  = (const float*)d_in[0];
    const float* Wq = (const float*)d_in[1];
    const float* Wk = (const float*)d_in[2];
    const float* Wv = (const float*)d_in[3];
    const float* Wo = (const float*)d_in[4];
    const float* rc = (const float*)d_in[5];
    const float* rs = (const float*)d_in[6];
    float* out = (float*)d_out;

    cudaFuncSetAttribute(attn_tc,
                         cudaFuncAttributeMaxDynamicSharedMemorySize, ATT_SMEM);

    dim3 ggrid(HDIM / 128, (BATCH * SEQ) / 128);   // (8, 32)
    gemm_tc<<<ggrid, 256>>>(x, Wq, nullptr, 1);
    gemm_tc<<<ggrid, 256>>>(x, Wk, nullptr, 2);
    gemm_tc<<<ggrid, 256>>>(x, Wv, nullptr, 3);

    rope_kernel<<<(BATCH * NHEADS * SEQ * 32) / 256, 256>>>(rc, rs);

    attn_tc<<<dim3(SEQ / 128, BATCH * NHEADS), 256, ATT_SMEM>>>();

    gemm_tc<<<ggrid, 256>>>(nullptr, Wo, out, 0);
}

// round 3
// speedup vs baseline: 2.9014x; 1.1409x over previous
#include <cuda_runtime.h>
#include <cstdint>

#define HDIM   1024
#define SEQ    2048
#define BATCH  2
#define NHEADS 16
#define HEADD  64

// Scratch (__device__ globals; no allocations allowed)
__device__ float g_q [BATCH*NHEADS*SEQ*HEADD];
__device__ float g_k [BATCH*NHEADS*SEQ*HEADD];
__device__ float g_v [BATCH*NHEADS*SEQ*HEADD];
__device__ float g_ao[BATCH*SEQ*HDIM];

// ---------------------------------------------------------------- helpers
__device__ __forceinline__ float f2tf(float x) {            // round-to-nearest tf32
    unsigned u; asm("cvt.rna.tf32.f32 %0,%1;" : "=r"(u) : "f"(x));
    return __uint_as_float(u);
}
__device__ __forceinline__ unsigned f2tfu(float x) {
    unsigned u; asm("cvt.rna.tf32.f32 %0,%1;" : "=r"(u) : "f"(x));
    return u;
}
__device__ __forceinline__ float ex2f(float x) {
    float r; asm("ex2.approx.f32 %0,%1;" : "=f"(r) : "f"(x)); return r;
}
__device__ __forceinline__ unsigned sptr(const void* p) {
    return (unsigned)__cvta_generic_to_shared(p);
}
__device__ __forceinline__ void ldsm4(unsigned a[4], unsigned addr) {
    asm volatile("ldmatrix.sync.aligned.m8n8.x4.shared.b16 {%0,%1,%2,%3}, [%4];"
        : "=r"(a[0]), "=r"(a[1]), "=r"(a[2]), "=r"(a[3]) : "r"(addr));
}
__device__ __forceinline__ void mma8(float c[4], const unsigned a[4], const unsigned b[2]) {
    asm volatile(
        "mma.sync.aligned.m16n8k8.row.col.f32.tf32.tf32.f32 "
        "{%0,%1,%2,%3}, {%4,%5,%6,%7}, {%8,%9}, {%0,%1,%2,%3};\n"
        : "+f"(c[0]), "+f"(c[1]), "+f"(c[2]), "+f"(c[3])
        : "r"(a[0]), "r"(a[1]), "r"(a[2]), "r"(a[3]), "r"(b[0]), "r"(b[1]));
}
__device__ __forceinline__ float4 cvt4(float4 v) {
    return make_float4(f2tf(v.x), f2tf(v.y), f2tf(v.z), f2tf(v.w));
}

// ---------------------------------------------------------------------------
// Tensor-core GEMM: C[m,n] = sum_k A[m,k] * W[n,k]
// Block 128x128, 8 warps (2x4 -> 64x32 warp tiles), K-step 16, double buffer.
// smem rows padded to 20 floats. dst_mode: 1/2/3 scatter into g_q/g_k/g_v.
// ---------------------------------------------------------------------------
__global__ __launch_bounds__(256) void gemm_tc(
    const float* __restrict__ A_in, const float* __restrict__ W,
    float* __restrict__ Cout, int dst_mode)
{
    __shared__ __align__(16) float As[2][128*20];
    __shared__ __align__(16) float Bs[2][128*20];

    const float* A = (dst_mode == 0) ? g_ao : A_in;
    const int m0 = blockIdx.y * 128, n0 = blockIdx.x * 128;
    const int t = threadIdx.x, lane = t & 31, wid = t >> 5;
    const int wm = (wid & 1) * 64, wn = (wid >> 1) * 32;

    const int grow = t >> 1;
    const int gcol = (t & 1) * 8;
    const float* Ag = A + (size_t)(m0 + grow) * HDIM + gcol;
    const float* Bg = W + (size_t)(n0 + grow) * HDIM + gcol;
    const int sst = grow * 20 + gcol;

    const int s = lane >> 3, r = lane & 7;
    const unsigned aAddr = sptr(&As[0][(wm + (s & 1) * 8 + r) * 20 + (s >> 1) * 4]);
    const unsigned bAddr = sptr(&Bs[0][(wn + (s >> 1) * 8 + r) * 20 + (s & 1) * 4]);

    float c[4][4][4];
    #pragma unroll
    for (int i = 0; i < 4; i++)
        #pragma unroll
        for (int j = 0; j < 4; j++)
            #pragma unroll
            for (int q = 0; q < 4; q++) c[i][j][q] = 0.f;

    float4 ra0 = *(const float4*)(Ag);
    float4 ra1 = *(const float4*)(Ag + 4);
    float4 rb0 = *(const float4*)(Bg);
    float4 rb1 = *(const float4*)(Bg + 4);
    *(float4*)(&As[0][sst])     = cvt4(ra0);
    *(float4*)(&As[0][sst + 4]) = cvt4(ra1);
    *(float4*)(&Bs[0][sst])     = cvt4(rb0);
    *(float4*)(&Bs[0][sst + 4]) = cvt4(rb1);
    __syncthreads();

    const int NIT = HDIM / 16;
    for (int it = 0; it < NIT; it++) {
        const int buf = it & 1;
        const bool pre = (it + 1 < NIT);
        if (pre) {
            const float* Ap = Ag + (it + 1) * 16;
            const float* Bp = Bg + (it + 1) * 16;
            ra0 = *(const float4*)(Ap);     ra1 = *(const float4*)(Ap + 4);
            rb0 = *(const float4*)(Bp);     rb1 = *(const float4*)(Bp + 4);
        }
        const unsigned bo = buf * (128 * 20 * 4);
        #pragma unroll
        for (int kc = 0; kc < 16; kc += 8) {
            unsigned aa[4][4], bb[2][4];
            #pragma unroll
            for (int mt = 0; mt < 4; mt++) ldsm4(aa[mt], aAddr + bo + mt * 1280 + kc * 4);
            #pragma unroll
            for (int p = 0; p < 2; p++)    ldsm4(bb[p], bAddr + bo + p * 1280 + kc * 4);
            #pragma unroll
            for (int mt = 0; mt < 4; mt++)
                #pragma unroll
                for (int nt = 0; nt < 4; nt++)
                    mma8(c[mt][nt], aa[mt], &bb[nt >> 1][(nt & 1) * 2]);
        }
        if (pre) {
            *(float4*)(&As[buf ^ 1][sst])     = cvt4(ra0);
            *(float4*)(&As[buf ^ 1][sst + 4]) = cvt4(ra1);
            *(float4*)(&Bs[buf ^ 1][sst])     = cvt4(rb0);
            *(float4*)(&Bs[buf ^ 1][sst + 4]) = cvt4(rb1);
        }
        __syncthreads();
    }

    const int grp = lane >> 2, tig = lane & 3;
    if (dst_mode == 0) {
        #pragma unroll
        for (int mt = 0; mt < 4; mt++)
            #pragma unroll
            for (int nt = 0; nt < 4; nt++) {
                int m = m0 + wm + mt * 16 + grp;
                int n = n0 + wn + nt * 8 + tig * 2;
                *(float2*)(Cout + (size_t)m * HDIM + n)       = make_float2(c[mt][nt][0], c[mt][nt][1]);
                *(float2*)(Cout + (size_t)(m + 8) * HDIM + n) = make_float2(c[mt][nt][2], c[mt][nt][3]);
            }
    } else {
        float* dst = (dst_mode == 1) ? g_q : (dst_mode == 2) ? g_k : g_v;
        #pragma unroll
        for (int mt = 0; mt < 4; mt++)
            #pragma unroll
            for (int nt = 0; nt < 4; nt++) {
                int m = m0 + wm + mt * 16 + grp;
                int n = n0 + wn + nt * 8 + tig * 2;
                int h = n >> 6, d = n & 63;
                int b = m >> 11, sq = m & (SEQ - 1);
                size_t off = (((size_t)(b * NHEADS + h) * SEQ) + sq) * HEADD + d;
                *(float2*)(dst + off)             = make_float2(c[mt][nt][0], c[mt][nt][1]);
                *(float2*)(dst + off + 8 * HEADD) = make_float2(c[mt][nt][2], c[mt][nt][3]);
            }
    }
}

// ---------------------------------------------------------------------------
__global__ __launch_bounds__(256) void rope_kernel(
    const float* __restrict__ rc, const float* __restrict__ rs)
{
    int idx = blockIdx.x * blockDim.x + threadIdx.x;
    int d  = idx & 31;
    int sq = (idx >> 5) & (SEQ - 1);
    int bh = idx >> 16;
    size_t base = ((size_t)bh * SEQ + sq) * HEADD;
    float cc = rc[sq * 32 + d];
    float ss = rs[sq * 32 + d];

    float q1 = g_q[base + d], q2 = g_q[base + d + 32];
    g_q[base + d]      = q1 * cc - q2 * ss;
    g_q[base + d + 32] = q2 * cc + q1 * ss;

    float k1 = g_k[base + d], k2 = g_k[base + d + 32];
    g_k[base + d]      = k1 * cc - k2 * ss;
    g_k[base + d + 32] = k2 * cc + k1 * ss;
}

// ---------------------------------------------------------------------------
// Flash attention v3: double-buffered K/V, register-shuffled P, shfl V-transpose.
// Block = (q-tile 128, bh). 256 thr, 8 warps, 2 blocks/SM.
// smem: Qs[128][68] | Ks[2][64][68] | Vt[2][64][68]  = 104448 B
// ---------------------------------------------------------------------------
#define ATT_SMEM ((128*68 + 4*64*68) * 4)   // 104448
#define KVBUF    (64*68)                    // floats per K/V buffer

__global__ __launch_bounds__(256, 2) void attn_tc()
{
    extern __shared__ __align__(16) float smf[];
    float* Qs  = smf;                       // 128*68
    float* Ks0 = smf + 128*68;              // 2 x 64*68
    float* Vt0 = smf + 128*68 + 2*KVBUF;    // 2 x 64*68

    const int bh = blockIdx.y, qt = blockIdx.x;
    const int t = threadIdx.x, lane = t & 31, wid = t >> 5;
    const int s = lane >> 3, r = lane & 7;
    const int grp = lane >> 2, tig = lane & 3;

    // ---- stage Q (scaled, tf32) into Qs
    const float* qp = g_q + ((size_t)bh * SEQ + qt * 128) * HEADD;
    const float QS = 0.125f * 1.4426950408889634f;   // scale * log2(e)
    #pragma unroll
    for (int it = 0; it < 8; it++) {
        int i = t + it * 256;
        int row = i >> 4, c4 = (i & 15) * 4;
        float4 v = *(const float4*)(qp + row * 64 + c4);
        *(float4*)(Qs + row * 68 + c4) =
            make_float4(f2tf(v.x * QS), f2tf(v.y * QS), f2tf(v.z * QS), f2tf(v.w * QS));
    }

    const float* kbase = g_k + (size_t)bh * SEQ * HEADD;
    const float* vbase = g_v + (size_t)bh * SEQ * HEADD;

    // staging maps
    const int krow = (t >> 4) & 63;                // rows 0..15 for it=0 (+16/iter)
    const int kc4  = (t & 15) * 4;
    const int j4 = lane & 3, g8 = lane >> 2;       // V-transpose group coords

    // ---- prologue: stage K0 / V0 into buffer 0
    {
        #pragma unroll
        for (int it = 0; it < 4; it++) {
            int row = krow + it * 16;
            float4 kv = *(const float4*)(kbase + row * 64 + kc4);
            *(float4*)(Ks0 + row * 68 + kc4) = cvt4(kv);
        }
        #pragma unroll
        for (int it = 0; it < 4; it++) {
            int task = it * 64 + wid * 8 + g8;
            int qr = task >> 4, qc = task & 15;
            float4 v = *(const float4*)(vbase + (qr * 4 + j4) * 64 + qc * 4);
            // 4x4 transpose across lanes j4=0..3
            float sA = (j4 & 1) ? v.x : v.y;
            float sB = (j4 & 1) ? v.z : v.w;
            float rA = __shfl_xor_sync(0xffffffffu, sA, 1);
            float rB = __shfl_xor_sync(0xffffffffu, sB, 1);
            float A0 = (j4 & 1) ? rA : v.x;
            float A1 = (j4 & 1) ? v.y : rA;
            float A2 = (j4 & 1) ? rB : v.z;
            float A3 = (j4 & 1) ? v.w : rB;
            float sC = (j4 & 2) ? A0 : A2;
            float sD = (j4 & 2) ? A1 : A3;
            float rC = __shfl_xor_sync(0xffffffffu, sC, 2);
            float rD = __shfl_xor_sync(0xffffffffu, sD, 2);
            float B0 = (j4 & 2) ? rC : A0;
            float B1 = (j4 & 2) ? rD : A1;
            float B2 = (j4 & 2) ? A2 : rC;
            float B3 = (j4 & 2) ? A3 : rD;
            *(float4*)(Vt0 + (qc * 4 + j4) * 68 + qr * 4) =
                make_float4(f2tf(B0), f2tf(B1), f2tf(B2), f2tf(B3));
        }
    }
    __syncthreads();

    const unsigned qA = sptr(Qs)  + ((wid * 16 + (s & 1) * 8 + r) * 68 + (s >> 1) * 4) * 4;
    const unsigned kA = sptr(Ks0) + (((s >> 1) * 8 + r) * 68 + (s & 1) * 4) * 4;
    const unsigned vA = sptr(Vt0) + (((s >> 1) * 8 + r) * 68 + (s & 1) * 4) * 4;
    const unsigned BUFB = KVBUF * 4;

    const int l0 = (lane & ~3) | (tig >> 1);
    const int l1 = l0 + 2;
    const bool odd = tig & 1;

    float o[8][4];
    #pragma unroll
    for (int nt = 0; nt < 8; nt++)
        { o[nt][0] = o[nt][1] = o[nt][2] = o[nt][3] = 0.f; }
    float m_u = -1e30f, m_d = -1e30f, l_u = 0.f, l_d = 0.f;

    for (int kt = 0; kt < SEQ / 64; kt++) {
        const int buf = kt & 1;
        const int kn = (kt < SEQ / 64 - 1) ? kt + 1 : kt;   // clamp (redundant load last iter)
        const float* kp = kbase + (size_t)kn * 64 * HEADD;
        const float* vp = vbase + (size_t)kn * 64 * HEADD;

        // prefetch next K tile into registers
        float4 kst[4];
        #pragma unroll
        for (int it = 0; it < 4; it++)
            kst[it] = *(const float4*)(kp + (krow + it * 16) * 64 + kc4);

        // ---- S = Q K^T (warp: 16 x 64) from Ks[buf]
        float sc[8][4];
        #pragma unroll
        for (int nt = 0; nt < 8; nt++)
            { sc[nt][0] = sc[nt][1] = sc[nt][2] = sc[nt][3] = 0.f; }
        #pragma unroll
        for (int kc = 0; kc < 8; kc++) {
            unsigned qf[4];
            ldsm4(qf, qA + kc * 32);
            unsigned kb[4][4];
            #pragma unroll
            for (int p = 0; p < 4; p++)
                ldsm4(kb[p], kA + buf * BUFB + p * (16*68*4) + kc * 32);
            #pragma unroll
            for (int nt = 0; nt < 8; nt++)
                mma8(sc[nt], qf, &kb[nt >> 1][(nt & 1) * 2]);
        }

        // store prefetched K into Ks[buf^1]
        #pragma unroll
        for (int it = 0; it < 4; it++)
            *(float4*)(Ks0 + (buf ^ 1) * KVBUF + (krow + it * 16) * 68 + kc4) = cvt4(kst[it]);

        // prefetch next V tile into registers
        float4 vst[4];
        #pragma unroll
        for (int it = 0; it < 4; it++) {
            int task = it * 64 + wid * 8 + g8;
            int qr = task >> 4, qc = task & 15;
            vst[it] = *(const float4*)(vp + (qr * 4 + j4) * 64 + qc * 4);
        }

        // ---- online softmax (rows grp and grp+8; reduce across 4 lanes)
        float mu = -1e30f, md = -1e30f;
        #pragma unroll
        for (int nt = 0; nt < 8; nt++) {
            mu = fmaxf(mu, fmaxf(sc[nt][0], sc[nt][1]));
            md = fmaxf(md, fmaxf(sc[nt][2], sc[nt][3]));
        }
        mu = fmaxf(mu, __shfl_xor_sync(0xffffffffu, mu, 1));
        mu = fmaxf(mu, __shfl_xor_sync(0xffffffffu, mu, 2));
        md = fmaxf(md, __shfl_xor_sync(0xffffffffu, md, 1));
        md = fmaxf(md, __shfl_xor_sync(0xffffffffu, md, 2));
        float mnu = fmaxf(m_u, mu), mnd = fmaxf(m_d, md);
        float au = ex2f(m_u - mnu), ad = ex2f(m_d - mnd);
        m_u = mnu; m_d = mnd;

        float su = 0.f, sd = 0.f;
        #pragma unroll
        for (int nt = 0; nt < 8; nt++) {
            sc[nt][0] = ex2f(sc[nt][0] - mnu);
            sc[nt][1] = ex2f(sc[nt][1] - mnu);
            sc[nt][2] = ex2f(sc[nt][2] - mnd);
            sc[nt][3] = ex2f(sc[nt][3] - mnd);
            su += sc[nt][0] + sc[nt][1];
            sd += sc[nt][2] + sc[nt][3];
        }
        su += __shfl_xor_sync(0xffffffffu, su, 1);
        su += __shfl_xor_sync(0xffffffffu, su, 2);
        sd += __shfl_xor_sync(0xffffffffu, sd, 1);
        sd += __shfl_xor_sync(0xffffffffu, sd, 2);
        l_u = l_u * au + su;
        l_d = l_d * ad + sd;
        #pragma unroll
        for (int nt = 0; nt < 8; nt++) {
            o[nt][0] *= au; o[nt][1] *= au;
            o[nt][2] *= ad; o[nt][3] *= ad;
        }

        // ---- O += P V : build A-fragments of P by intra-warp shuffle
        #pragma unroll
        for (int kc = 0; kc < 8; kc++) {
            float r00 = __shfl_sync(0xffffffffu, sc[kc][0], l0);
            float r01 = __shfl_sync(0xffffffffu, sc[kc][1], l0);
            float r02 = __shfl_sync(0xffffffffu, sc[kc][2], l0);
            float r03 = __shfl_sync(0xffffffffu, sc[kc][3], l0);
            float r10 = __shfl_sync(0xffffffffu, sc[kc][0], l1);
            float r11 = __shfl_sync(0xffffffffu, sc[kc][1], l1);
            float r12 = __shfl_sync(0xffffffffu, sc[kc][2], l1);
            float r13 = __shfl_sync(0xffffffffu, sc[kc][3], l1);
            unsigned af[4];
            af[0] = f2tfu(odd ? r01 : r00);
            af[1] = f2tfu(odd ? r03 : r02);
            af[2] = f2tfu(odd ? r11 : r10);
            af[3] = f2tfu(odd ? r13 : r12);
            unsigned vb[4][4];
            #pragma unroll
            for (int p = 0; p < 4; p++)
                ldsm4(vb[p], vA + buf * BUFB + p * (16*68*4) + kc * 32);
            #pragma unroll
            for (int nt = 0; nt < 8; nt++)
                mma8(o[nt], af, &vb[nt >> 1][(nt & 1) * 2]);
        }

        // ---- transpose + store prefetched V into Vt[buf^1]
        #pragma unroll
        for (int it = 0; it < 4; it++) {
            int task = it * 64 + wid * 8 + g8;
            int qr = task >> 4, qc = task & 15;
            float4 v = vst[it];
            float sA = (j4 & 1) ? v.x : v.y;
            float sB = (j4 & 1) ? v.z : v.w;
            float rA = __shfl_xor_sync(0xffffffffu, sA, 1);
            float rB = __shfl_xor_sync(0xffffffffu, sB, 1);
            float A0 = (j4 & 1) ? rA : v.x;
            float A1 = (j4 & 1) ? v.y : rA;
            float A2 = (j4 & 1) ? rB : v.z;
            float A3 = (j4 & 1) ? v.w : rB;
            float sC = (j4 & 2) ? A0 : A2;
            float sD = (j4 & 2) ? A1 : A3;
            float rC = __shfl_xor_sync(0xffffffffu, sC, 2);
            float rD = __shfl_xor_sync(0xffffffffu, sD, 2);
            float B0 = (j4 & 2) ? rC : A0;
            float B1 = (j4 & 2) ? rD : A1;
            float B2 = (j4 & 2) ? A2 : rC;
            float B3 = (j4 & 2) ? A3 : rD;
            *(float4*)(Vt0 + (buf ^ 1) * KVBUF + (qc * 4 + j4) * 68 + qr * 4) =
                make_float4(f2tf(B0), f2tf(B1), f2tf(B2), f2tf(B3));
        }
        __syncthreads();
    }

    // ---- epilogue: normalize, write g_ao [B,S,H]
    const int b = bh >> 4, h = bh & 15;
    const float iu = 1.f / l_u, id = 1.f / l_d;
    const int srow = qt * 128 + wid * 16 + grp;
    float* obase = g_ao + ((size_t)(b * SEQ + srow)) * HDIM + h * HEADD;
    #pragma unroll
    for (int nt = 0; nt < 8; nt++) {
        int d = nt * 8 + tig * 2;
        *(float2*)(obase + d)            = make_float2(o[nt][0] * iu, o[nt][1] * iu);
        *(float2*)(obase + 8 * HDIM + d) = make_float2(o[nt][2] * id, o[nt][3] * id);
    }
}

// ---------------------------------------------------------------------------
extern "C" void kernel_launch(void* const* d_in, const int* in_sizes, int n_in,
                              void* d_out, int out_size)
{
    const float* x  = (const float*)d_in[0];
    const float* Wq = (const float*)d_in[1];
    const float* Wk = (const float*)d_in[2];
    const float* Wv = (const float*)d_in[3];
    const float* Wo = (const float*)d_in[4];
    const float* rc = (const float*)d_in[5];
    const float* rs = (const float*)d_in[6];
    float* out = (float*)d_out;

    cudaFuncSetAttribute(attn_tc,
                         cudaFuncAttributeMaxDynamicSharedMemorySize, ATT_SMEM);

    dim3 ggrid(HDIM / 128, (BATCH * SEQ) / 128);   // (8, 32)
    gemm_tc<<<ggrid, 256>>>(x, Wq, nullptr, 1);
    gemm_tc<<<ggrid, 256>>>(x, Wk, nullptr, 2);
    gemm_tc<<<ggrid, 256>>>(x, Wv, nullptr, 3);

    rope_kernel<<<(BATCH * NHEADS * SEQ * 32) / 256, 256>>>(rc, rs);

    attn_tc<<<dim3(SEQ / 128, BATCH * NHEADS), 256, ATT_SMEM>>>();

    gemm_tc<<<ggrid, 256>>>(nullptr, Wo, out, 0);
}

// round 4
// speedup vs baseline: 4.2537x; 1.4661x over previous
#include <cuda_runtime.h>
#include <cuda_fp16.h>
#include <cstdint>

#define HDIM   1024
#define SEQ    2048
#define BATCH  2
#define NHEADS 16
#define HEADD  64

// Scratch (__device__ globals; no allocations allowed)
__device__ float g_q [BATCH*NHEADS*SEQ*HEADD];
__device__ float g_k [BATCH*NHEADS*SEQ*HEADD];
__device__ float g_v [BATCH*NHEADS*SEQ*HEADD];
__device__ float g_ao[BATCH*SEQ*HDIM];

// ---------------------------------------------------------------- helpers
__device__ __forceinline__ float ex2f(float x) {
    float r; asm("ex2.approx.f32 %0,%1;" : "=f"(r) : "f"(x)); return r;
}
__device__ __forceinline__ unsigned sptr(const void* p) {
    return (unsigned)__cvta_generic_to_shared(p);
}
__device__ __forceinline__ void ldsm4(unsigned a[4], unsigned addr) {
    asm volatile("ldmatrix.sync.aligned.m8n8.x4.shared.b16 {%0,%1,%2,%3}, [%4];"
        : "=r"(a[0]), "=r"(a[1]), "=r"(a[2]), "=r"(a[3]) : "r"(addr));
}
__device__ __forceinline__ void mma16(float c[4], const unsigned a[4],
                                      unsigned b0, unsigned b1) {
    asm volatile(
        "mma.sync.aligned.m16n8k16.row.col.f32.f16.f16.f32 "
        "{%0,%1,%2,%3}, {%4,%5,%6,%7}, {%8,%9}, {%0,%1,%2,%3};\n"
        : "+f"(c[0]), "+f"(c[1]), "+f"(c[2]), "+f"(c[3])
        : "r"(a[0]), "r"(a[1]), "r"(a[2]), "r"(a[3]), "r"(b0), "r"(b1));
}
__device__ __forceinline__ unsigned pack2(float a, float b) {
    __half2 h = __floats2half2_rn(a, b);
    return *reinterpret_cast<unsigned*>(&h);
}
__device__ __forceinline__ uint4 pack8(float4 a, float4 b) {
    uint4 r;
    r.x = pack2(a.x, a.y); r.y = pack2(a.z, a.w);
    r.z = pack2(b.x, b.y); r.w = pack2(b.z, b.w);
    return r;
}

// ---------------------------------------------------------------------------
// fp16 tensor-core GEMM: C[m,n] = sum_k A[m,k] * W[n,k], fp32 accum.
// Block 128x128, 8 warps (2x4 -> 64x32 warp tiles), K-step 32, double buffer.
// smem rows: 32 halves + pad -> stride 40 halves (80B: conflict-free ldmatrix).
// dst_mode: 1/2/3 scatter into g_q/g_k/g_v in [b,h,s,d]; 0 -> Cout row-major.
// ---------------------------------------------------------------------------
#define GSTR 40

__global__ __launch_bounds__(256) void gemm_tc(
    const float* __restrict__ A_in, const float* __restrict__ W,
    float* __restrict__ Cout, int dst_mode)
{
    __shared__ __align__(16) __half As[2][128*GSTR];
    __shared__ __align__(16) __half Bs[2][128*GSTR];

    const float* A = (dst_mode == 0) ? g_ao : A_in;
    const int m0 = blockIdx.y * 128, n0 = blockIdx.x * 128;
    const int t = threadIdx.x, lane = t & 31, wid = t >> 5;
    const int wm = (wid & 1) * 64, wn = (wid >> 1) * 32;

    const int grow = t >> 1;
    const int gcol = (t & 1) * 16;
    const float* Ag = A + (size_t)(m0 + grow) * HDIM + gcol;
    const float* Bg = W + (size_t)(n0 + grow) * HDIM + gcol;
    const int sst = grow * GSTR + gcol;

    const int s = lane >> 3, r = lane & 7;
    const unsigned aAddr = sptr(&As[0][(wm + (s & 1) * 8 + r) * GSTR + (s >> 1) * 8]);
    const unsigned bAddr = sptr(&Bs[0][(wn + (s & 1) * 8 + r) * GSTR + (s >> 1) * 8]);

    float c[4][4][4];
    #pragma unroll
    for (int i = 0; i < 4; i++)
        #pragma unroll
        for (int j = 0; j < 4; j++)
            #pragma unroll
            for (int q = 0; q < 4; q++) c[i][j][q] = 0.f;

    float4 ra[4], rb[4];
    #pragma unroll
    for (int i = 0; i < 4; i++) {
        ra[i] = *(const float4*)(Ag + i * 4);
        rb[i] = *(const float4*)(Bg + i * 4);
    }
    *(uint4*)(&As[0][sst])     = pack8(ra[0], ra[1]);
    *(uint4*)(&As[0][sst + 8]) = pack8(ra[2], ra[3]);
    *(uint4*)(&Bs[0][sst])     = pack8(rb[0], rb[1]);
    *(uint4*)(&Bs[0][sst + 8]) = pack8(rb[2], rb[3]);
    __syncthreads();

    const int NIT = HDIM / 32;
    for (int it = 0; it < NIT; it++) {
        const int buf = it & 1;
        const bool pre = (it + 1 < NIT);
        if (pre) {
            const float* Ap = Ag + (it + 1) * 32;
            const float* Bp = Bg + (it + 1) * 32;
            #pragma unroll
            for (int i = 0; i < 4; i++) {
                ra[i] = *(const float4*)(Ap + i * 4);
                rb[i] = *(const float4*)(Bp + i * 4);
            }
        }
        const unsigned bo = buf * (128 * GSTR * 2);
        #pragma unroll
        for (int kc = 0; kc < 2; kc++) {
            unsigned aa[4][4], bb[2][4];
            #pragma unroll
            for (int mt = 0; mt < 4; mt++)
                ldsm4(aa[mt], aAddr + bo + mt * (16 * GSTR * 2) + kc * 32);
            #pragma unroll
            for (int p = 0; p < 2; p++)
                ldsm4(bb[p], bAddr + bo + p * (16 * GSTR * 2) + kc * 32);
            #pragma unroll
            for (int mt = 0; mt < 4; mt++)
                #pragma unroll
                for (int nt = 0; nt < 4; nt++)
                    mma16(c[mt][nt], aa[mt],
                          bb[nt >> 1][(nt & 1) ? 1 : 0],
                          bb[nt >> 1][(nt & 1) ? 3 : 2]);
        }
        if (pre) {
            *(uint4*)(&As[buf ^ 1][sst])     = pack8(ra[0], ra[1]);
            *(uint4*)(&As[buf ^ 1][sst + 8]) = pack8(ra[2], ra[3]);
            *(uint4*)(&Bs[buf ^ 1][sst])     = pack8(rb[0], rb[1]);
            *(uint4*)(&Bs[buf ^ 1][sst + 8]) = pack8(rb[2], rb[3]);
        }
        __syncthreads();
    }

    const int grp = lane >> 2, tig = lane & 3;
    if (dst_mode == 0) {
        #pragma unroll
        for (int mt = 0; mt < 4; mt++)
            #pragma unroll
            for (int nt = 0; nt < 4; nt++) {
                int m = m0 + wm + mt * 16 + grp;
                int n = n0 + wn + nt * 8 + tig * 2;
                *(float2*)(Cout + (size_t)m * HDIM + n)       = make_float2(c[mt][nt][0], c[mt][nt][1]);
                *(float2*)(Cout + (size_t)(m + 8) * HDIM + n) = make_float2(c[mt][nt][2], c[mt][nt][3]);
            }
    } else {
        float* dst = (dst_mode == 1) ? g_q : (dst_mode == 2) ? g_k : g_v;
        #pragma unroll
        for (int mt = 0; mt < 4; mt++)
            #pragma unroll
            for (int nt = 0; nt < 4; nt++) {
                int m = m0 + wm + mt * 16 + grp;
                int n = n0 + wn + nt * 8 + tig * 2;
                int h = n >> 6, d = n & 63;
                int b = m >> 11, sq = m & (SEQ - 1);
                size_t off = (((size_t)(b * NHEADS + h) * SEQ) + sq) * HEADD + d;
                *(float2*)(dst + off)             = make_float2(c[mt][nt][0], c[mt][nt][1]);
                *(float2*)(dst + off + 8 * HEADD) = make_float2(c[mt][nt][2], c[mt][nt][3]);
            }
    }
}

// ---------------------------------------------------------------------------
__global__ __launch_bounds__(256) void rope_kernel(
    const float* __restrict__ rc, const float* __restrict__ rs)
{
    int idx = blockIdx.x * blockDim.x + threadIdx.x;
    int d  = idx & 31;
    int sq = (idx >> 5) & (SEQ - 1);
    int bh = idx >> 16;
    size_t base = ((size_t)bh * SEQ + sq) * HEADD;
    float cc = rc[sq * 32 + d];
    float ss = rs[sq * 32 + d];

    float q1 = g_q[base + d], q2 = g_q[base + d + 32];
    g_q[base + d]      = q1 * cc - q2 * ss;
    g_q[base + d + 32] = q2 * cc + q1 * ss;

    float k1 = g_k[base + d], k2 = g_k[base + d + 32];
    g_k[base + d]      = k1 * cc - k2 * ss;
    g_k[base + d + 32] = k2 * cc + k1 * ss;
}

// ---------------------------------------------------------------------------
// Flash attention, fp16 mma. Block = (q-tile 128, bh). 256 thr, 2 blocks/SM.
// smem (halves, stride 72 = 144B rows): Qs[128][72] | Ks[2][64][72] | Vt[2][64][72]
// P's A-fragments come straight from S's C-fragments (no shuffles, no smem).
// ---------------------------------------------------------------------------
#define ASTR 72
#define KVH  (64*ASTR)                 // halves per K/V buffer
#define ATT_SMEM ((128*ASTR + 4*KVH) * 2)   // 55296 B

__global__ __launch_bounds__(256, 2) void attn_tc()
{
    extern __shared__ __align__(16) __half smh[];
    __half* Qs  = smh;                   // 128*72
    __half* Ks0 = smh + 128*ASTR;        // 2 x 64*72
    __half* Vt0 = smh + 128*ASTR + 2*KVH;

    const int bh = blockIdx.y, qt = blockIdx.x;
    const int t = threadIdx.x, lane = t & 31, wid = t >> 5;
    const int s = lane >> 3, r = lane & 7;
    const int grp = lane >> 2, tig = lane & 3;

    // ---- stage Q (scaled) into Qs as fp16
    const float* qp = g_q + ((size_t)bh * SEQ + qt * 128) * HEADD;
    const float QS = 0.125f * 1.4426950408889634f;   // scale * log2(e)
    #pragma unroll
    for (int it = 0; it < 8; it++) {
        int i = t + it * 256;
        int row = i >> 4, c4 = (i & 15) * 4;
        float4 v = *(const float4*)(qp + row * 64 + c4);
        *(uint2*)(Qs + row * ASTR + c4) =
            make_uint2(pack2(v.x * QS, v.y * QS), pack2(v.z * QS, v.w * QS));
    }

    const float* kbase = g_k + (size_t)bh * SEQ * HEADD;
    const float* vbase = g_v + (size_t)bh * SEQ * HEADD;

    const int krow = t >> 4;                 // 0..15 (+16 per it)
    const int kc4  = (t & 15) * 4;
    const int j4 = lane & 3, g8 = lane >> 2; // V-transpose coords

    // ---- prologue: stage K0 / V0 into buffer 0
    {
        #pragma unroll
        for (int it = 0; it < 4; it++) {
            int row = krow + it * 16;
            float4 kv = *(const float4*)(kbase + row * 64 + kc4);
            *(uint2*)(Ks0 + row * ASTR + kc4) =
                make_uint2(pack2(kv.x, kv.y), pack2(kv.z, kv.w));
        }
        #pragma unroll
        for (int it = 0; it < 4; it++) {
            int task = it * 64 + wid * 8 + g8;
            int qr = task >> 4, qc = task & 15;
            float4 v = *(const float4*)(vbase + (qr * 4 + j4) * 64 + qc * 4);
            float sA = (j4 & 1) ? v.x : v.y;
            float sB = (j4 & 1) ? v.z : v.w;
            float rA = __shfl_xor_sync(0xffffffffu, sA, 1);
            float rB = __shfl_xor_sync(0xffffffffu, sB, 1);
            float A0 = (j4 & 1) ? rA : v.x;
            float A1 = (j4 & 1) ? v.y : rA;
            float A2 = (j4 & 1) ? rB : v.z;
            float A3 = (j4 & 1) ? v.w : rB;
            float sC = (j4 & 2) ? A0 : A2;
            float sD = (j4 & 2) ? A1 : A3;
            float rC = __shfl_xor_sync(0xffffffffu, sC, 2);
            float rD = __shfl_xor_sync(0xffffffffu, sD, 2);
            float B0 = (j4 & 2) ? rC : A0;
            float B1 = (j4 & 2) ? rD : A1;
            float B2 = (j4 & 2) ? A2 : rC;
            float B3 = (j4 & 2) ? A3 : rD;
            *(uint2*)(Vt0 + (qc * 4 + j4) * ASTR + qr * 4) =
                make_uint2(pack2(B0, B1), pack2(B2, B3));
        }
    }
    __syncthreads();

    const unsigned qA = sptr(Qs)  + ((wid * 16 + (s & 1) * 8 + r) * ASTR + (s >> 1) * 8) * 2;
    const unsigned kA = sptr(Ks0) + (((s & 1) * 8 + r) * ASTR + (s >> 1) * 8) * 2;
    const unsigned vA = sptr(Vt0) + (((s & 1) * 8 + r) * ASTR + (s >> 1) * 8) * 2;
    const unsigned BUFB = KVH * 2;

    float o[8][4];
    #pragma unroll
    for (int nt = 0; nt < 8; nt++)
        { o[nt][0] = o[nt][1] = o[nt][2] = o[nt][3] = 0.f; }
    float m_u = -1e30f, m_d = -1e30f, l_u = 0.f, l_d = 0.f;

    for (int kt = 0; kt < SEQ / 64; kt++) {
        const int buf = kt & 1;
        const int kn = (kt < SEQ / 64 - 1) ? kt + 1 : kt;   // clamp
        const float* kp = kbase + (size_t)kn * 64 * HEADD;
        const float* vp = vbase + (size_t)kn * 64 * HEADD;

        // prefetch next K tile (convert at load: 8 regs)
        uint2 kst[4];
        #pragma unroll
        for (int it = 0; it < 4; it++) {
            float4 kv = *(const float4*)(kp + (krow + it * 16) * 64 + kc4);
            kst[it] = make_uint2(pack2(kv.x, kv.y), pack2(kv.z, kv.w));
        }

        // ---- S = Q K^T (warp: 16 x 64) from Ks[buf]
        float sc[8][4];
        #pragma unroll
        for (int nt = 0; nt < 8; nt++)
            { sc[nt][0] = sc[nt][1] = sc[nt][2] = sc[nt][3] = 0.f; }
        #pragma unroll
        for (int kc = 0; kc < 4; kc++) {
            unsigned qf[4];
            ldsm4(qf, qA + kc * 32);
            unsigned kb[4][4];
            #pragma unroll
            for (int p = 0; p < 4; p++)
                ldsm4(kb[p], kA + buf * BUFB + p * (16 * ASTR * 2) + kc * 32);
            #pragma unroll
            for (int nt = 0; nt < 8; nt++)
                mma16(sc[nt], qf,
                      kb[nt >> 1][(nt & 1) ? 1 : 0],
                      kb[nt >> 1][(nt & 1) ? 3 : 2]);
        }

        // store prefetched K into Ks[buf^1]
        #pragma unroll
        for (int it = 0; it < 4; it++)
            *(uint2*)(Ks0 + (buf ^ 1) * KVH + (krow + it * 16) * ASTR + kc4) = kst[it];

        // prefetch next V tile
        float4 vst[4];
        #pragma unroll
        for (int it = 0; it < 4; it++) {
            int task = it * 64 + wid * 8 + g8;
            int qr = task >> 4, qc = task & 15;
            vst[it] = *(const float4*)(vp + (qr * 4 + j4) * 64 + qc * 4);
        }

        // ---- online softmax (rows grp and grp+8; reduce across 4 lanes)
        float mu = -1e30f, md = -1e30f;
        #pragma unroll
        for (int nt = 0; nt < 8; nt++) {
            mu = fmaxf(mu, fmaxf(sc[nt][0], sc[nt][1]));
            md = fmaxf(md, fmaxf(sc[nt][2], sc[nt][3]));
        }
        mu = fmaxf(mu, __shfl_xor_sync(0xffffffffu, mu, 1));
        mu = fmaxf(mu, __shfl_xor_sync(0xffffffffu, mu, 2));
        md = fmaxf(md, __shfl_xor_sync(0xffffffffu, md, 1));
        md = fmaxf(md, __shfl_xor_sync(0xffffffffu, md, 2));
        float mnu = fmaxf(m_u, mu), mnd = fmaxf(m_d, md);
        float au = ex2f(m_u - mnu), ad = ex2f(m_d - mnd);
        m_u = mnu; m_d = mnd;

        float su = 0.f, sd = 0.f;
        #pragma unroll
        for (int nt = 0; nt < 8; nt++) {
            sc[nt][0] = ex2f(sc[nt][0] - mnu);
            sc[nt][1] = ex2f(sc[nt][1] - mnu);
            sc[nt][2] = ex2f(sc[nt][2] - mnd);
            sc[nt][3] = ex2f(sc[nt][3] - mnd);
            su += sc[nt][0] + sc[nt][1];
            sd += sc[nt][2] + sc[nt][3];
        }
        su += __shfl_xor_sync(0xffffffffu, su, 1);
        su += __shfl_xor_sync(0xffffffffu, su, 2);
        sd += __shfl_xor_sync(0xffffffffu, sd, 1);
        sd += __shfl_xor_sync(0xffffffffu, sd, 2);
        l_u = l_u * au + su;
        l_d = l_d * ad + sd;
        #pragma unroll
        for (int nt = 0; nt < 8; nt++) {
            o[nt][0] *= au; o[nt][1] *= au;
            o[nt][2] *= ad; o[nt][3] *= ad;
        }

        // ---- O += P V : P A-fragments are repacked S C-fragments (no shfl!)
        #pragma unroll
        for (int kc = 0; kc < 4; kc++) {
            unsigned af[4];
            af[0] = pack2(sc[2*kc][0],   sc[2*kc][1]);
            af[1] = pack2(sc[2*kc][2],   sc[2*kc][3]);
            af[2] = pack2(sc[2*kc+1][0], sc[2*kc+1][1]);
            af[3] = pack2(sc[2*kc+1][2], sc[2*kc+1][3]);
            unsigned vb[4][4];
            #pragma unroll
            for (int p = 0; p < 4; p++)
                ldsm4(vb[p], vA + buf * BUFB + p * (16 * ASTR * 2) + kc * 32);
            #pragma unroll
            for (int nt = 0; nt < 8; nt++)
                mma16(o[nt], af,
                      vb[nt >> 1][(nt & 1) ? 1 : 0],
                      vb[nt >> 1][(nt & 1) ? 3 : 2]);
        }

        // ---- transpose + store prefetched V into Vt[buf^1]
        #pragma unroll
        for (int it = 0; it < 4; it++) {
            int task = it * 64 + wid * 8 + g8;
            int qr = task >> 4, qc = task & 15;
            float4 v = vst[it];
            float sA = (j4 & 1) ? v.x : v.y;
            float sB = (j4 & 1) ? v.z : v.w;
            float rA = __shfl_xor_sync(0xffffffffu, sA, 1);
            float rB = __shfl_xor_sync(0xffffffffu, sB, 1);
            float A0 = (j4 & 1) ? rA : v.x;
            float A1 = (j4 & 1) ? v.y : rA;
            float A2 = (j4 & 1) ? rB : v.z;
            float A3 = (j4 & 1) ? v.w : rB;
            float sC = (j4 & 2) ? A0 : A2;
            float sD = (j4 & 2) ? A1 : A3;
            float rC = __shfl_xor_sync(0xffffffffu, sC, 2);
            float rD = __shfl_xor_sync(0xffffffffu, sD, 2);
            float B0 = (j4 & 2) ? rC : A0;
            float B1 = (j4 & 2) ? rD : A1;
            float B2 = (j4 & 2) ? A2 : rC;
            float B3 = (j4 & 2) ? A3 : rD;
            *(uint2*)(Vt0 + (buf ^ 1) * KVH + (qc * 4 + j4) * ASTR + qr * 4) =
                make_uint2(pack2(B0, B1), pack2(B2, B3));
        }
        __syncthreads();
    }

    // ---- epilogue: normalize, write g_ao [B,S,H]
    const int b = bh >> 4, h = bh & 15;
    const float iu = 1.f / l_u, id = 1.f / l_d;
    const int srow = qt * 128 + wid * 16 + grp;
    float* obase = g_ao + ((size_t)(b * SEQ + srow)) * HDIM + h * HEADD;
    #pragma unroll
    for (int nt = 0; nt < 8; nt++) {
        int d = nt * 8 + tig * 2;
        *(float2*)(obase + d)            = make_float2(o[nt][0] * iu, o[nt][1] * iu);
        *(float2*)(obase + 8 * HDIM + d) = make_float2(o[nt][2] * id, o[nt][3] * id);
    }
}

// ---------------------------------------------------------------------------
extern "C" void kernel_launch(void* const* d_in, const int* in_sizes, int n_in,
                              void* d_out, int out_size)
{
    const float* x  = (const float*)d_in[0];
    const float* Wq = (const float*)d_in[1];
    const float* Wk = (const float*)d_in[2];
    const float* Wv = (const float*)d_in[3];
    const float* Wo = (const float*)d_in[4];
    const float* rc = (const float*)d_in[5];
    const float* rs = (const float*)d_in[6];
    float* out = (float*)d_out;

    cudaFuncSetAttribute(attn_tc,
                         cudaFuncAttributeMaxDynamicSharedMemorySize, ATT_SMEM);

    dim3 ggrid(HDIM / 128, (BATCH * SEQ) / 128);   // (8, 32)
    gemm_tc<<<ggrid, 256>>>(x, Wq, nullptr, 1);
    gemm_tc<<<ggrid, 256>>>(x, Wk, nullptr, 2);
    gemm_tc<<<ggrid, 256>>>(x, Wv, nullptr, 3);

    rope_kernel<<<(BATCH * NHEADS * SEQ * 32) / 256, 256>>>(rc, rs);

    attn_tc<<<dim3(SEQ / 128, BATCH * NHEADS), 256, ATT_SMEM>>>();

    gemm_tc<<<ggrid, 256>>>(nullptr, Wo, out, 0);
}

// round 7
// speedup vs baseline: 5.1087x; 1.2010x over previous
#include <cuda_runtime.h>
#include <cuda_fp16.h>
#include <cstdint>

#define HDIM   1024
#define SEQ    2048
#define BATCH  2
#define NHEADS 16
#define HEADD  64

// Scratch (__device__ globals; no allocations allowed)
__device__ float  g_q  [BATCH*NHEADS*SEQ*HEADD];   // f32 Q projection (pre-rope)
__device__ float  g_k  [BATCH*NHEADS*SEQ*HEADD];   // f32 K projection (pre-rope)
__device__ __half g_qh [BATCH*NHEADS*SEQ*HEADD];   // fp16 Q (post-rope)
__device__ __half g_kh [BATCH*NHEADS*SEQ*HEADD];   // fp16 K (post-rope)
__device__ __half g_vh [BATCH*NHEADS*SEQ*HEADD];   // fp16 V
__device__ __half g_aoh[BATCH*SEQ*HDIM];           // fp16 attention output
__device__ __half g_xh [BATCH*SEQ*HDIM];           // fp16 x
__device__ __half g_wh [4][HDIM*HDIM];             // fp16 Wq,Wk,Wv,Wo

// ---------------------------------------------------------------- helpers
__device__ __forceinline__ float ex2f(float x) {
    float r; asm("ex2.approx.f32 %0,%1;" : "=f"(r) : "f"(x)); return r;
}
__device__ __forceinline__ unsigned sptr(const void* p) {
    return (unsigned)__cvta_generic_to_shared(p);
}
__device__ __forceinline__ void ldsm4(unsigned a[4], unsigned addr) {
    asm volatile("ldmatrix.sync.aligned.m8n8.x4.shared.b16 {%0,%1,%2,%3}, [%4];"
        : "=r"(a[0]), "=r"(a[1]), "=r"(a[2]), "=r"(a[3]) : "r"(addr));
}
__device__ __forceinline__ void ldsm4t(unsigned a[4], unsigned addr) {
    asm volatile("ldmatrix.sync.aligned.m8n8.x4.trans.shared.b16 {%0,%1,%2,%3}, [%4];"
        : "=r"(a[0]), "=r"(a[1]), "=r"(a[2]), "=r"(a[3]) : "r"(addr));
}
__device__ __forceinline__ void mma16(float c[4], const unsigned a[4],
                                      unsigned b0, unsigned b1) {
    asm volatile(
        "mma.sync.aligned.m16n8k16.row.col.f32.f16.f16.f32 "
        "{%0,%1,%2,%3}, {%4,%5,%6,%7}, {%8,%9}, {%0,%1,%2,%3};\n"
        : "+f"(c[0]), "+f"(c[1]), "+f"(c[2]), "+f"(c[3])
        : "r"(a[0]), "r"(a[1]), "r"(a[2]), "r"(a[3]), "r"(b0), "r"(b1));
}
__device__ __forceinline__ unsigned pack2(float a, float b) {
    __half2 h = __floats2half2_rn(a, b);
    return *reinterpret_cast<unsigned*>(&h);
}
__device__ __forceinline__ uint4 pack8(float4 a, float4 b) {
    uint4 r;
    r.x = pack2(a.x, a.y); r.y = pack2(a.z, a.w);
    r.z = pack2(b.x, b.y); r.w = pack2(b.z, b.w);
    return r;
}
__device__ __forceinline__ void cpa16(unsigned d, const void* s) {
    asm volatile("cp.async.cg.shared.global [%0], [%1], 16;\n" :: "r"(d), "l"(s));
}
__device__ __forceinline__ void cp_commit() {
    asm volatile("cp.async.commit_group;\n");
}
template<int N> __device__ __forceinline__ void cp_wait() {
    asm volatile("cp.async.wait_group %0;\n" :: "n"(N));
}

// ---------------------------------------------------------------------------
// f32 -> fp16 bulk convert. 8 elems/thread. tgt: 0=x, 1..4=Wq,Wk,Wv,Wo
// ---------------------------------------------------------------------------
__global__ __launch_bounds__(256) void cvt_h(const float* __restrict__ in, int tgt)
{
    __half* out = (tgt == 0) ? g_xh : g_wh[tgt - 1];
    int i = blockIdx.x * 256 + threadIdx.x;
    float4 a = ((const float4*)in)[2*i];
    float4 b = ((const float4*)in)[2*i + 1];
    ((uint4*)out)[i] = pack8(a, b);
}

// ---------------------------------------------------------------------------
// Pure-fp16 tensor-core GEMM: C[m,n] = sum_k A[m,k] * W[n,k], fp32 accum.
// Block 128x128, 8 warps, K-step 32, cp.async double buffer, stride 40 halves.
// mode: 1/2 -> f32 scatter g_q/g_k;  3 -> fp16 scatter g_vh;  0 -> f32 outF.
// ---------------------------------------------------------------------------
#define GSTR 40

__global__ __launch_bounds__(256) void gemm_tc(float* __restrict__ outF, int mode)
{
    __shared__ __align__(16) __half As[2][128*GSTR];
    __shared__ __align__(16) __half Bs[2][128*GSTR];

    const __half* A = (mode == 0) ? g_aoh : g_xh;
    const __half* B = g_wh[(mode == 0) ? 3 : (mode - 1)];

    const int m0 = blockIdx.y * 128, n0 = blockIdx.x * 128;
    const int t = threadIdx.x, lane = t & 31, wid = t >> 5;
    const int wm = (wid & 1) * 64, wn = (wid >> 1) * 32;

    const int grow = t >> 1;
    const int gcol = (t & 1) * 16;
    const __half* Ag = A + (size_t)(m0 + grow) * HDIM + gcol;
    const __half* Bg = B + (size_t)(n0 + grow) * HDIM + gcol;
    const unsigned aSt = sptr(&As[0][grow * GSTR + gcol]);
    const unsigned bSt = sptr(&Bs[0][grow * GSTR + gcol]);
    const unsigned BUFO = 128 * GSTR * 2;

    const int s = lane >> 3, r = lane & 7;
    const unsigned aAddr = sptr(&As[0][(wm + (s & 1) * 8 + r) * GSTR + (s >> 1) * 8]);
    const unsigned bAddr = sptr(&Bs[0][(wn + (s & 1) * 8 + r) * GSTR + (s >> 1) * 8]);

    float c[4][4][4];
    #pragma unroll
    for (int i = 0; i < 4; i++)
        #pragma unroll
        for (int j = 0; j < 4; j++)
            #pragma unroll
            for (int q = 0; q < 4; q++) c[i][j][q] = 0.f;

    // prologue: slab 0
    cpa16(aSt,      Ag);     cpa16(aSt + 16, Ag + 8);
    cpa16(bSt,      Bg);     cpa16(bSt + 16, Bg + 8);
    cp_commit();

    const int NIT = HDIM / 32;
    for (int it = 0; it < NIT; it++) {
        const int buf = it & 1;
        if (it + 1 < NIT) {
            const __half* Ap = Ag + (it + 1) * 32;
            const __half* Bp = Bg + (it + 1) * 32;
            const unsigned o = (buf ^ 1) * BUFO;
            cpa16(aSt + o,      Ap);     cpa16(aSt + o + 16, Ap + 8);
            cpa16(bSt + o,      Bp);     cpa16(bSt + o + 16, Bp + 8);
            cp_commit();
            cp_wait<1>();
        } else {
            cp_wait<0>();
        }
        __syncthreads();

        const unsigned bo = buf * BUFO;
        #pragma unroll
        for (int kc = 0; kc < 2; kc++) {
            unsigned aa[4][4], bb[2][4];
            #pragma unroll
            for (int mt = 0; mt < 4; mt++)
                ldsm4(aa[mt], aAddr + bo + mt * (16 * GSTR * 2) + kc * 32);
            #pragma unroll
            for (int p = 0; p < 2; p++)
                ldsm4(bb[p], bAddr + bo + p * (16 * GSTR * 2) + kc * 32);
            #pragma unroll
            for (int mt = 0; mt < 4; mt++)
                #pragma unroll
                for (int nt = 0; nt < 4; nt++)
                    mma16(c[mt][nt], aa[mt],
                          bb[nt >> 1][(nt & 1) ? 1 : 0],
                          bb[nt >> 1][(nt & 1) ? 3 : 2]);
        }
        __syncthreads();
    }

    const int grp = lane >> 2, tig = lane & 3;
    if (mode == 0) {
        #pragma unroll
        for (int mt = 0; mt < 4; mt++)
            #pragma unroll
            for (int nt = 0; nt < 4; nt++) {
                int m = m0 + wm + mt * 16 + grp;
                int n = n0 + wn + nt * 8 + tig * 2;
                *(float2*)(outF + (size_t)m * HDIM + n)       = make_float2(c[mt][nt][0], c[mt][nt][1]);
                *(float2*)(outF + (size_t)(m + 8) * HDIM + n) = make_float2(c[mt][nt][2], c[mt][nt][3]);
            }
    } else if (mode == 3) {
        #pragma unroll
        for (int mt = 0; mt < 4; mt++)
            #pragma unroll
            for (int nt = 0; nt < 4; nt++) {
                int m = m0 + wm + mt * 16 + grp;
                int n = n0 + wn + nt * 8 + tig * 2;
                int h = n >> 6, d = n & 63;
                int b = m >> 11, sq = m & (SEQ - 1);
                size_t off = (((size_t)(b * NHEADS + h) * SEQ) + sq) * HEADD + d;
                *(unsigned*)(g_vh + off)             = pack2(c[mt][nt][0], c[mt][nt][1]);
                *(unsigned*)(g_vh + off + 8 * HEADD) = pack2(c[mt][nt][2], c[mt][nt][3]);
            }
    } else {
        float* dst = (mode == 1) ? g_q : g_k;
        #pragma unroll
        for (int mt = 0; mt < 4; mt++)
            #pragma unroll
            for (int nt = 0; nt < 4; nt++) {
                int m = m0 + wm + mt * 16 + grp;
                int n = n0 + wn + nt * 8 + tig * 2;
                int h = n >> 6, d = n & 63;
                int b = m >> 11, sq = m & (SEQ - 1);
                size_t off = (((size_t)(b * NHEADS + h) * SEQ) + sq) * HEADD + d;
                *(float2*)(dst + off)             = make_float2(c[mt][nt][0], c[mt][nt][1]);
                *(float2*)(dst + off + 8 * HEADD) = make_float2(c[mt][nt][2], c[mt][nt][3]);
            }
    }
}

// ---------------------------------------------------------------------------
// RoPE: read f32 g_q/g_k, write fp16 g_qh/g_kh (single rounding point).
// ---------------------------------------------------------------------------
__global__ __launch_bounds__(256) void rope_kernel(
    const float* __restrict__ rc, const float* __restrict__ rs)
{
    int idx = blockIdx.x * blockDim.x + threadIdx.x;
    int d  = idx & 31;
    int sq = (idx >> 5) & (SEQ - 1);
    int bh = idx >> 16;
    size_t base = ((size_t)bh * SEQ + sq) * HEADD;
    float cc = rc[sq * 32 + d];
    float ss = rs[sq * 32 + d];

    float q1 = g_q[base + d], q2 = g_q[base + d + 32];
    g_qh[base + d]      = __float2half(q1 * cc - q2 * ss);
    g_qh[base + d + 32] = __float2half(q2 * cc + q1 * ss);

    float k1 = g_k[base + d], k2 = g_k[base + d + 32];
    g_kh[base + d]      = __float2half(k1 * cc - k2 * ss);
    g_kh[base + d + 32] = __float2half(k2 * cc + k1 * ss);
}

// ---------------------------------------------------------------------------
// Flash attention, pure fp16 smem via cp.async; ldmatrix.trans for V (no
// transpose pass). Block = (q-tile 128, bh). 256 thr, 8 warps, 2 blocks/SM.
// smem halves (stride 72): Qs[128][72] | Ks[2][64][72] | Vs[2][64][72]
// Scale folded into softmax: p = ex2(fma(s, SC, -m*SC)).
// ---------------------------------------------------------------------------
#define ASTR 72
#define KVH  (64*ASTR)
#define ATT_SMEM ((128*ASTR + 4*KVH) * 2)   // 55296 B

__global__ __launch_bounds__(256, 2) void attn_tc()
{
    extern __shared__ __align__(16) __half smh[];
    __half* Qs  = smh;                   // 128*72
    __half* Ks0 = smh + 128*ASTR;        // 2 x 64*72
    __half* Vs0 = Ks0 + 2*KVH;           // 2 x 64*72   [s][d] row-major

    const int bh = blockIdx.y, qt = blockIdx.x;
    const int t = threadIdx.x, lane = t & 31, wid = t >> 5;
    const int s = lane >> 3, r = lane & 7;
    const int grp = lane >> 2, tig = lane & 3;

    const __half* qp    = g_qh + ((size_t)bh * SEQ + qt * 128) * HEADD;
    const __half* kbase = g_kh + (size_t)bh * SEQ * HEADD;
    const __half* vbase = g_vh + (size_t)bh * SEQ * HEADD;

    // ---- prologue: Q (4 chunks) + K0/V0 (2 chunks each) in one group
    {
        const unsigned qDst = sptr(Qs) + ((t >> 1) * ASTR + (t & 1) * 32) * 2;
        const __half* qsrc = qp + (t >> 1) * HEADD + (t & 1) * 32;
        #pragma unroll
        for (int j = 0; j < 4; j++) cpa16(qDst + j * 16, qsrc + j * 8);
    }
    const unsigned kDst = sptr(Ks0) + ((t >> 2) * ASTR + (t & 3) * 16) * 2;
    const unsigned vDst = sptr(Vs0) + ((t >> 2) * ASTR + (t & 3) * 16) * 2;
    const int srcoff = (t >> 2) * HEADD + (t & 3) * 16;
    cpa16(kDst,      kbase + srcoff);     cpa16(kDst + 16, kbase + srcoff + 8);
    cpa16(vDst,      vbase + srcoff);     cpa16(vDst + 16, vbase + srcoff + 8);
    cp_commit();

    const unsigned qA = sptr(Qs)  + ((wid * 16 + (s & 1) * 8 + r) * ASTR + (s >> 1) * 8) * 2;
    const unsigned kA = sptr(Ks0) + (((s & 1) * 8 + r) * ASTR + (s >> 1) * 8) * 2;
    const unsigned vA = sptr(Vs0) + (((s & 1) * 8 + r) * ASTR + (s >> 1) * 8) * 2;
    const unsigned BUFB = KVH * 2;

    const float SC = 0.125f * 1.4426950408889634f;   // scale * log2(e)

    float o[8][4];
    #pragma unroll
    for (int nt = 0; nt < 8; nt++)
        { o[nt][0] = o[nt][1] = o[nt][2] = o[nt][3] = 0.f; }
    float m_u = -1e30f, m_d = -1e30f, l_u = 0.f, l_d = 0.f;

    for (int kt = 0; kt < SEQ / 64; kt++) {
        const int buf = kt & 1;
        const int kn = (kt < SEQ / 64 - 1) ? kt + 1 : kt;   // clamp (redundant last)
        const size_t toff = (size_t)kn * 64 * HEADD;
        const unsigned nb = (buf ^ 1) * BUFB;
        cpa16(kDst + nb,      kbase + toff + srcoff);
        cpa16(kDst + nb + 16, kbase + toff + srcoff + 8);
        cpa16(vDst + nb,      vbase + toff + srcoff);
        cpa16(vDst + nb + 16, vbase + toff + srcoff + 8);
        cp_commit();
        cp_wait<1>();
        __syncthreads();

        // ---- S = Q K^T (warp: 16 x 64) from Ks[buf]
        float sc[8][4];
        #pragma unroll
        for (int nt = 0; nt < 8; nt++)
            { sc[nt][0] = sc[nt][1] = sc[nt][2] = sc[nt][3] = 0.f; }
        #pragma unroll
        for (int kc = 0; kc < 4; kc++) {
            unsigned qf[4];
            ldsm4(qf, qA + kc * 32);
            unsigned kb[4][4];
            #pragma unroll
            for (int p = 0; p < 4; p++)
                ldsm4(kb[p], kA + buf * BUFB + p * (16 * ASTR * 2) + kc * 32);
            #pragma unroll
            for (int nt = 0; nt < 8; nt++)
                mma16(sc[nt], qf,
                      kb[nt >> 1][(nt & 1) ? 1 : 0],
                      kb[nt >> 1][(nt & 1) ? 3 : 2]);
        }

        // ---- online softmax (rows grp, grp+8; reduce across 4 lanes)
        float mu = -1e30f, md = -1e30f;
        #pragma unroll
        for (int nt = 0; nt < 8; nt++) {
            mu = fmaxf(mu, fmaxf(sc[nt][0], sc[nt][1]));
            md = fmaxf(md, fmaxf(sc[nt][2], sc[nt][3]));
        }
        mu = fmaxf(mu, __shfl_xor_sync(0xffffffffu, mu, 1));
        mu = fmaxf(mu, __shfl_xor_sync(0xffffffffu, mu, 2));
        md = fmaxf(md, __shfl_xor_sync(0xffffffffu, md, 1));
        md = fmaxf(md, __shfl_xor_sync(0xffffffffu, md, 2));
        float mnu = fmaxf(m_u, mu), mnd = fmaxf(m_d, md);
        float au = ex2f((m_u - mnu) * SC), ad = ex2f((m_d - mnd) * SC);
        m_u = mnu; m_d = mnd;
        const float bu = -mnu * SC, bd = -mnd * SC;

        float su = 0.f, sd = 0.f;
        #pragma unroll
        for (int nt = 0; nt < 8; nt++) {
            sc[nt][0] = ex2f(fmaf(sc[nt][0], SC, bu));
            sc[nt][1] = ex2f(fmaf(sc[nt][1], SC, bu));
            sc[nt][2] = ex2f(fmaf(sc[nt][2], SC, bd));
            sc[nt][3] = ex2f(fmaf(sc[nt][3], SC, bd));
            su += sc[nt][0] + sc[nt][1];
            sd += sc[nt][2] + sc[nt][3];
        }
        su += __shfl_xor_sync(0xffffffffu, su, 1);
        su += __shfl_xor_sync(0xffffffffu, su, 2);
        sd += __shfl_xor_sync(0xffffffffu, sd, 1);
        sd += __shfl_xor_sync(0xffffffffu, sd, 2);
        l_u = l_u * au + su;
        l_d = l_d * ad + sd;
        #pragma unroll
        for (int nt = 0; nt < 8; nt++) {
            o[nt][0] *= au; o[nt][1] *= au;
            o[nt][2] *= ad; o[nt][3] *= ad;
        }

        // ---- O += P V : A-frags = repacked S; B-frags via ldmatrix.trans
        #pragma unroll
        for (int kc = 0; kc < 4; kc++) {
            unsigned af[4];
            af[0] = pack2(sc[2*kc][0],   sc[2*kc][1]);
            af[1] = pack2(sc[2*kc][2],   sc[2*kc][3]);
            af[2] = pack2(sc[2*kc+1][0], sc[2*kc+1][1]);
            af[3] = pack2(sc[2*kc+1][2], sc[2*kc+1][3]);
            #pragma unroll
            for (int p = 0; p < 4; p++) {
                unsigned vb[4];
                ldsm4t(vb, vA + buf * BUFB + kc * (16 * ASTR * 2) + p * 32);
                mma16(o[2*p],   af, vb[0], vb[1]);
                mma16(o[2*p+1], af, vb[2], vb[3]);
            }
        }
        __syncthreads();
    }
    cp_wait<0>();

    // ---- epilogue: normalize, write fp16 g_aoh [B,S,H]
    const int b = bh >> 4, h = bh & 15;
    const float iu = 1.f / l_u, id = 1.f / l_d;
    const int srow = qt * 128 + wid * 16 + grp;
    __half* obase = g_aoh + ((size_t)(b * SEQ + srow)) * HDIM + h * HEADD;
    #pragma unroll
    for (int nt = 0; nt < 8; nt++) {
        int d = nt * 8 + tig * 2;
        *(unsigned*)(obase + d)            = pack2(o[nt][0] * iu, o[nt][1] * iu);
        *(unsigned*)(obase + 8 * HDIM + d) = pack2(o[nt][2] * id, o[nt][3] * id);
    }
}

// ---------------------------------------------------------------------------
extern "C" void kernel_launch(void* const* d_in, const int* in_sizes, int n_in,
                              void* d_out, int out_size)
{
    const float* x  = (const float*)d_in[0];
    const float* Wq = (const float*)d_in[1];
    const float* Wk = (const float*)d_in[2];
    const float* Wv = (const float*)d_in[3];
    const float* Wo = (const float*)d_in[4];
    const float* rc = (const float*)d_in[5];
    const float* rs = (const float*)d_in[6];
    float* out = (float*)d_out;

    cudaFuncSetAttribute(attn_tc,
                         cudaFuncAttributeMaxDynamicSharedMemorySize, ATT_SMEM);

    // fp16 pre-conversion (x: 4M elems, W: 1M each; 8 elems/thread)
    cvt_h<<<(BATCH*SEQ*HDIM/8 + 255)/256, 256>>>(x,  0);
    cvt_h<<<(HDIM*HDIM/8 + 255)/256,      256>>>(Wq, 1);
    cvt_h<<<(HDIM*HDIM/8 + 255)/256,      256>>>(Wk, 2);
    cvt_h<<<(HDIM*HDIM/8 + 255)/256,      256>>>(Wv, 3);
    cvt_h<<<(HDIM*HDIM/8 + 255)/256,      256>>>(Wo, 4);

    dim3 ggrid(HDIM / 128, (BATCH * SEQ) / 128);   // (8, 32)
    gemm_tc<<<ggrid, 256>>>(nullptr, 1);   // Q -> g_q (f32)
    gemm_tc<<<ggrid, 256>>>(nullptr, 2);   // K -> g_k (f32)
    gemm_tc<<<ggrid, 256>>>(nullptr, 3);   // V -> g_vh (fp16)

    rope_kernel<<<(BATCH * NHEADS * SEQ * 32) / 256, 256>>>(rc, rs);

    attn_tc<<<dim3(SEQ / 128, BATCH * NHEADS), 256, ATT_SMEM>>>();

    gemm_tc<<<ggrid, 256>>>(out, 0);       // Wo GEMM -> f32 out
}

// round 10
// speedup vs baseline: 5.4976x; 1.0761x over previous
#include <cuda_runtime.h>
#include <cuda_fp16.h>
#include <cstdint>

#define HDIM   1024
#define SEQ    2048
#define BATCH  2
#define NHEADS 16
#define HEADD  64

// Scratch (__device__ globals; no allocations allowed)
__device__ __half g_qh [BATCH*NHEADS*SEQ*HEADD];   // fp16 Q (post-rope)
__device__ __half g_kh [BATCH*NHEADS*SEQ*HEADD];   // fp16 K (post-rope)
__device__ __half g_vh [BATCH*NHEADS*SEQ*HEADD];   // fp16 V
__device__ __half g_aoh[BATCH*SEQ*HDIM];           // fp16 attention output
__device__ __half g_xh [BATCH*SEQ*HDIM];           // fp16 x
__device__ __half g_wh [4][HDIM*HDIM];             // fp16 Wq,Wk,Wv,Wo

// ---------------------------------------------------------------- helpers
__device__ __forceinline__ float ex2f(float x) {
    float r; asm("ex2.approx.f32 %0,%1;" : "=f"(r) : "f"(x)); return r;
}
__device__ __forceinline__ unsigned sptr(const void* p) {
    return (unsigned)__cvta_generic_to_shared(p);
}
__device__ __forceinline__ void ldsm4(unsigned a[4], unsigned addr) {
    asm volatile("ldmatrix.sync.aligned.m8n8.x4.shared.b16 {%0,%1,%2,%3}, [%4];"
        : "=r"(a[0]), "=r"(a[1]), "=r"(a[2]), "=r"(a[3]) : "r"(addr));
}
__device__ __forceinline__ void ldsm4t(unsigned a[4], unsigned addr) {
    asm volatile("ldmatrix.sync.aligned.m8n8.x4.trans.shared.b16 {%0,%1,%2,%3}, [%4];"
        : "=r"(a[0]), "=r"(a[1]), "=r"(a[2]), "=r"(a[3]) : "r"(addr));
}
__device__ __forceinline__ void mma16(float c[4], const unsigned a[4],
                                      unsigned b0, unsigned b1) {
    asm volatile(
        "mma.sync.aligned.m16n8k16.row.col.f32.f16.f16.f32 "
        "{%0,%1,%2,%3}, {%4,%5,%6,%7}, {%8,%9}, {%0,%1,%2,%3};\n"
        : "+f"(c[0]), "+f"(c[1]), "+f"(c[2]), "+f"(c[3])
        : "r"(a[0]), "r"(a[1]), "r"(a[2]), "r"(a[3]), "r"(b0), "r"(b1));
}
__device__ __forceinline__ unsigned pack2(float a, float b) {
    __half2 h = __floats2half2_rn(a, b);
    return *reinterpret_cast<unsigned*>(&h);
}
__device__ __forceinline__ uint4 pack8(float4 a, float4 b) {
    uint4 r;
    r.x = pack2(a.x, a.y); r.y = pack2(a.z, a.w);
    r.z = pack2(b.x, b.y); r.w = pack2(b.z, b.w);
    return r;
}
__device__ __forceinline__ void cpa16(unsigned d, const void* s) {
    asm volatile("cp.async.cg.shared.global [%0], [%1], 16;\n" :: "r"(d), "l"(s));
}
__device__ __forceinline__ void cp_commit() {
    asm volatile("cp.async.commit_group;\n");
}
template<int N> __device__ __forceinline__ void cp_wait() {
    asm volatile("cp.async.wait_group %0;\n" :: "n"(N));
}

// ---------------------------------------------------------------------------
// f32 -> fp16 bulk convert, all tensors in ONE launch (uint4 chunks of 8).
// chunks: [0, 512K) = x ; then 4 x 128K = Wq, Wk, Wv, Wo
// ---------------------------------------------------------------------------
__global__ __launch_bounds__(256) void cvt_all(
    const float* __restrict__ x,  const float* __restrict__ wq,
    const float* __restrict__ wk, const float* __restrict__ wv,
    const float* __restrict__ wo)
{
    int i = blockIdx.x * 256 + threadIdx.x;
    const float* src; __half* dst; int base;
    if (i < 524288) { src = x; dst = g_xh; base = i; }
    else {
        int j = i - 524288;
        int w = j >> 17;  base = j & 131071;
        src = (w == 0) ? wq : (w == 1) ? wk : (w == 2) ? wv : wo;
        dst = g_wh[w];
    }
    float4 a = ((const float4*)src)[2*base];
    float4 b = ((const float4*)src)[2*base + 1];
    ((uint4*)dst)[base] = pack8(a, b);
}

// ---------------------------------------------------------------------------
// fp16 mma.sync GEMM: C[m,n] = sum_k A[m,k] * W[n,k], fp32 accum.
// Block 128x128, 8 warps with 32(M)x64(N) warp tiles -> each warp covers a
// full head (d 0..63), so the RoPE pair (d, d+32) sits in ONE thread:
// c[mt][nt] / c[mt][nt+4]. K-step 32, 3-stage cp.async pipeline.
// mode: 1/2 -> rope + fp16 scatter g_qh/g_kh; 3 -> fp16 scatter g_vh;
//       0 -> f32 outF row-major.
// ---------------------------------------------------------------------------
#define GSTR 40
#define GBUFO (128*GSTR*2)              // bytes per A (or B) stage buffer
#define GT_SMEM (6*GBUFO)               // 3 stages x (A+B) = 61440 B

__global__ __launch_bounds__(256) void gemm_tc(
    float* __restrict__ outF,
    const float* __restrict__ rc, const float* __restrict__ rs, int mode)
{
    extern __shared__ __align__(16) __half gsm[];
    __half* As = gsm;                    // 3 x 128*GSTR
    __half* Bs = gsm + 3*128*GSTR;

    const __half* A = (mode == 0) ? g_aoh : g_xh;
    const __half* B = g_wh[(mode == 0) ? 3 : (mode - 1)];

    const int m0 = blockIdx.y * 128, n0 = blockIdx.x * 128;
    const int t = threadIdx.x, lane = t & 31, wid = t >> 5;
    const int wm = (wid & 3) * 32, wn = (wid >> 2) * 64;

    const int grow = t >> 1;
    const int gcol = (t & 1) * 16;
    const __half* Ag = A + (size_t)(m0 + grow) * HDIM + gcol;
    const __half* Bg = B + (size_t)(n0 + grow) * HDIM + gcol;
    const unsigned aSt = sptr(&As[grow * GSTR + gcol]);
    const unsigned bSt = sptr(&Bs[grow * GSTR + gcol]);

    const int s = lane >> 3, r = lane & 7;
    const unsigned aAddr = sptr(&As[(wm + (s & 1) * 8 + r) * GSTR + (s >> 1) * 8]);
    const unsigned bAddr = sptr(&Bs[(wn + (s & 1) * 8 + r) * GSTR + (s >> 1) * 8]);

    float c[2][8][4];
    #pragma unroll
    for (int i = 0; i < 2; i++)
        #pragma unroll
        for (int j = 0; j < 8; j++)
            #pragma unroll
            for (int q = 0; q < 4; q++) c[i][j][q] = 0.f;

    #define G_LOAD(sl, buf) do { \
        const __half* _as = Ag + (sl) * 32; \
        const __half* _bs = Bg + (sl) * 32; \
        unsigned _o = (buf) * GBUFO; \
        cpa16(aSt + _o,      _as);    cpa16(aSt + _o + 16, _as + 8); \
        cpa16(bSt + _o,      _bs);    cpa16(bSt + _o + 16, _bs + 8); \
        cp_commit(); \
    } while (0)

    G_LOAD(0, 0);
    G_LOAD(1, 1);

    const int NIT = HDIM / 32;
    for (int it = 0; it < NIT; it++) {
        const int buf = it % 3;
        cp_wait<1>();
        __syncthreads();
        if (it + 2 < NIT) G_LOAD(it + 2, (it + 2) % 3);
        else              cp_commit();            // keep group count aligned

        const unsigned bo = buf * GBUFO;
        #pragma unroll
        for (int kc = 0; kc < 2; kc++) {
            unsigned aa[2][4], bb[4][4];
            #pragma unroll
            for (int mt = 0; mt < 2; mt++)
                ldsm4(aa[mt], aAddr + bo + mt * (16 * GSTR * 2) + kc * 32);
            #pragma unroll
            for (int p = 0; p < 4; p++)
                ldsm4(bb[p], bAddr + bo + p * (16 * GSTR * 2) + kc * 32);
            #pragma unroll
            for (int mt = 0; mt < 2; mt++)
                #pragma unroll
                for (int nt = 0; nt < 8; nt++)
                    mma16(c[mt][nt], aa[mt],
                          bb[nt >> 1][(nt & 1) ? 1 : 0],
                          bb[nt >> 1][(nt & 1) ? 3 : 2]);
        }
    }
    cp_wait<0>();

    const int grp = lane >> 2, tig = lane & 3;
    if (mode == 0) {
        #pragma unroll
        for (int mt = 0; mt < 2; mt++)
            #pragma unroll
            for (int nt = 0; nt < 8; nt++) {
                int m = m0 + wm + mt * 16 + grp;
                int n = n0 + wn + nt * 8 + tig * 2;
                *(float2*)(outF + (size_t)m * HDIM + n)       = make_float2(c[mt][nt][0], c[mt][nt][1]);
                *(float2*)(outF + (size_t)(m + 8) * HDIM + n) = make_float2(c[mt][nt][2], c[mt][nt][3]);
            }
    } else if (mode == 3) {
        const int h = (n0 + wn) >> 6;
        #pragma unroll
        for (int mt = 0; mt < 2; mt++)
            #pragma unroll
            for (int nt = 0; nt < 8; nt++) {
                int m = m0 + wm + mt * 16 + grp;
                int d = nt * 8 + tig * 2;
                int b = m >> 11, sq = m & (SEQ - 1);
                size_t off = (((size_t)(b * NHEADS + h) * SEQ) + sq) * HEADD + d;
                *(unsigned*)(g_vh + off)             = pack2(c[mt][nt][0], c[mt][nt][1]);
                *(unsigned*)(g_vh + off + 8 * HEADD) = pack2(c[mt][nt][2], c[mt][nt][3]);
            }
    } else {
        // RoPE fused: pair (d, d+32) = (c[mt][nt], c[mt][nt+4]), nt < 4.
        __half* dst = (mode == 1) ? g_qh : g_kh;
        const int h = (n0 + wn) >> 6;
        #pragma unroll
        for (int mt = 0; mt < 2; mt++) {
            #pragma unroll
            for (int half = 0; half < 2; half++) {       // rows grp, grp+8
                int m  = m0 + wm + mt * 16 + grp + half * 8;
                int b  = m >> 11, sq = m & (SEQ - 1);
                size_t base = (((size_t)(b * NHEADS + h) * SEQ) + sq) * HEADD;
                const float* rcp = rc + sq * 32;
                const float* rsp = rs + sq * 32;
                const int q0 = half * 2;                 // c idx 0/1 or 2/3
                #pragma unroll
                for (int nt = 0; nt < 4; nt++) {
                    int d0 = nt * 8 + tig * 2;
                    float cc0 = rcp[d0],     ss0 = rsp[d0];
                    float cc1 = rcp[d0 + 1], ss1 = rsp[d0 + 1];
                    float x1a = c[mt][nt][q0],     x2a = c[mt][nt + 4][q0];
                    float x1b = c[mt][nt][q0 + 1], x2b = c[mt][nt + 4][q0 + 1];
                    *(unsigned*)(dst + base + d0) =
                        pack2(x1a * cc0 - x2a * ss0, x1b * cc1 - x2b * ss1);
                    *(unsigned*)(dst + base + d0 + 32) =
                        pack2(x2a * cc0 + x1a * ss0, x2b * cc1 + x1b * ss1);
                }
            }
        }
    }
}

// ---------------------------------------------------------------------------
// Flash attention: fp16 smem via 3-deep cp.async KV pipeline, ldmatrix.trans
// for V. Block = (q-tile 128, bh). 256 thr, 8 warps, 2 blocks/SM.
// smem halves (stride 72): Qs[128][72] | Ks[3][64][72] | Vs[3][64][72]
// ---------------------------------------------------------------------------
#define ASTR 72
#define KVH  (64*ASTR)
#define BUFB (KVH*2)
#define ATT_SMEM ((128*ASTR + 6*KVH) * 2)   // 73728 B

__global__ __launch_bounds__(256, 2) void attn_tc()
{
    extern __shared__ __align__(16) __half smh[];
    __half* Qs  = smh;                   // 128*72
    __half* Ks0 = smh + 128*ASTR;        // 3 x 64*72
    __half* Vs0 = Ks0 + 3*KVH;           // 3 x 64*72

    const int bh = blockIdx.y, qt = blockIdx.x;
    const int t = threadIdx.x, lane = t & 31, wid = t >> 5;
    const int s = lane >> 3, r = lane & 7;
    const int grp = lane >> 2, tig = lane & 3;

    const __half* qp    = g_qh + ((size_t)bh * SEQ + qt * 128) * HEADD;
    const __half* kbase = g_kh + (size_t)bh * SEQ * HEADD;
    const __half* vbase = g_vh + (size_t)bh * SEQ * HEADD;

    // ---- prologue: group0 = Q + K0/V0 ; group1 = K1/V1
    {
        const unsigned qDst = sptr(Qs) + ((t >> 1) * ASTR + (t & 1) * 32) * 2;
        const __half* qsrc = qp + (t >> 1) * HEADD + (t & 1) * 32;
        #pragma unroll
        for (int j = 0; j < 4; j++) cpa16(qDst + j * 16, qsrc + j * 8);
    }
    const unsigned kDst = sptr(Ks0) + ((t >> 2) * ASTR + (t & 3) * 16) * 2;
    const unsigned vDst = sptr(Vs0) + ((t >> 2) * ASTR + (t & 3) * 16) * 2;
    const int srcoff = (t >> 2) * HEADD + (t & 3) * 16;
    cpa16(kDst,      kbase + srcoff);     cpa16(kDst + 16, kbase + srcoff + 8);
    cpa16(vDst,      vbase + srcoff);     cpa16(vDst + 16, vbase + srcoff + 8);
    cp_commit();
    {
        const size_t t1 = (size_t)64 * HEADD;
        cpa16(kDst + BUFB,      kbase + t1 + srcoff);
        cpa16(kDst + BUFB + 16, kbase + t1 + srcoff + 8);
        cpa16(vDst + BUFB,      vbase + t1 + srcoff);
        cpa16(vDst + BUFB + 16, vbase + t1 + srcoff + 8);
        cp_commit();
    }

    const unsigned qA = sptr(Qs)  + ((wid * 16 + (s & 1) * 8 + r) * ASTR + (s >> 1) * 8) * 2;
    const unsigned kA = sptr(Ks0) + (((s & 1) * 8 + r) * ASTR + (s >> 1) * 8) * 2;
    const unsigned vA = sptr(Vs0) + (((s & 1) * 8 + r) * ASTR + (s >> 1) * 8) * 2;

    const float SC = 0.125f * 1.4426950408889634f;

    float o[8][4];
    #pragma unroll
    for (int nt = 0; nt < 8; nt++)
        { o[nt][0] = o[nt][1] = o[nt][2] = o[nt][3] = 0.f; }
    float m_u = -1e30f, m_d = -1e30f, l_u = 0.f, l_d = 0.f;

    const int NT = SEQ / 64;
    for (int kt = 0; kt < NT; kt++) {
        const int buf = kt % 3;
        cp_wait<1>();
        __syncthreads();

        // issue tile kt+2 into buffer (kt+2)%3 (clamped; never a live buffer)
        {
            const int kn = (kt + 2 < NT) ? kt + 2 : NT - 1;
            const size_t toff = (size_t)kn * 64 * HEADD;
            const unsigned nb = ((kt + 2) % 3) * BUFB;
            cpa16(kDst + nb,      kbase + toff + srcoff);
            cpa16(kDst + nb + 16, kbase + toff + srcoff + 8);
            cpa16(vDst + nb,      vbase + toff + srcoff);
            cpa16(vDst + nb + 16, vbase + toff + srcoff + 8);
            cp_commit();
        }

        // ---- S = Q K^T (warp: 16 x 64)
        float sc[8][4];
        #pragma unroll
        for (int nt = 0; nt < 8; nt++)
            { sc[nt][0] = sc[nt][1] = sc[nt][2] = sc[nt][3] = 0.f; }
        #pragma unroll
        for (int kc = 0; kc < 4; kc++) {
            unsigned qf[4];
            ldsm4(qf, qA + kc * 32);
            unsigned kb[4][4];
            #pragma unroll
            for (int p = 0; p < 4; p++)
                ldsm4(kb[p], kA + buf * BUFB + p * (16 * ASTR * 2) + kc * 32);
            #pragma unroll
            for (int nt = 0; nt < 8; nt++)
                mma16(sc[nt], qf,
                      kb[nt >> 1][(nt & 1) ? 1 : 0],
                      kb[nt >> 1][(nt & 1) ? 3 : 2]);
        }

        // ---- online softmax (rows grp, grp+8; reduce across 4 lanes)
        float mu = -1e30f, md = -1e30f;
        #pragma unroll
        for (int nt = 0; nt < 8; nt++) {
            mu = fmaxf(mu, fmaxf(sc[nt][0], sc[nt][1]));
            md = fmaxf(md, fmaxf(sc[nt][2], sc[nt][3]));
        }
        mu = fmaxf(mu, __shfl_xor_sync(0xffffffffu, mu, 1));
        mu = fmaxf(mu, __shfl_xor_sync(0xffffffffu, mu, 2));
        md = fmaxf(md, __shfl_xor_sync(0xffffffffu, md, 1));
        md = fmaxf(md, __shfl_xor_sync(0xffffffffu, md, 2));
        float mnu = fmaxf(m_u, mu), mnd = fmaxf(m_d, md);
        float au = ex2f((m_u - mnu) * SC), ad = ex2f((m_d - mnd) * SC);
        m_u = mnu; m_d = mnd;
        const float bu = -mnu * SC, bd = -mnd * SC;

        float su = 0.f, sd = 0.f;
        #pragma unroll
        for (int nt = 0; nt < 8; nt++) {
            sc[nt][0] = ex2f(fmaf(sc[nt][0], SC, bu));
            sc[nt][1] = ex2f(fmaf(sc[nt][1], SC, bu));
            sc[nt][2] = ex2f(fmaf(sc[nt][2], SC, bd));
            sc[nt][3] = ex2f(fmaf(sc[nt][3], SC, bd));
            su += sc[nt][0] + sc[nt][1];
            sd += sc[nt][2] + sc[nt][3];
        }
        su += __shfl_xor_sync(0xffffffffu, su, 1);
        su += __shfl_xor_sync(0xffffffffu, su, 2);
        sd += __shfl_xor_sync(0xffffffffu, sd, 1);
        sd += __shfl_xor_sync(0xffffffffu, sd, 2);
        l_u = l_u * au + su;
        l_d = l_d * ad + sd;
        #pragma unroll
        for (int nt = 0; nt < 8; nt++) {
            o[nt][0] *= au; o[nt][1] *= au;
            o[nt][2] *= ad; o[nt][3] *= ad;
        }

        // ---- O += P V : A-frags = repacked S; B-frags via ldmatrix.trans
        #pragma unroll
        for (int kc = 0; kc < 4; kc++) {
            unsigned af[4];
            af[0] = pack2(sc[2*kc][0],   sc[2*kc][1]);
            af[1] = pack2(sc[2*kc][2],   sc[2*kc][3]);
            af[2] = pack2(sc[2*kc+1][0], sc[2*kc+1][1]);
            af[3] = pack2(sc[2*kc+1][2], sc[2*kc+1][3]);
            #pragma unroll
            for (int p = 0; p < 4; p++) {
                unsigned vb[4];
                ldsm4t(vb, vA + buf * BUFB + kc * (16 * ASTR * 2) + p * 32);
                mma16(o[2*p],   af, vb[0], vb[1]);
                mma16(o[2*p+1], af, vb[2], vb[3]);
            }
        }
    }
    cp_wait<0>();

    // ---- epilogue: normalize, write fp16 g_aoh [B,S,H]
    const int b = bh >> 4, h = bh & 15;
    const float iu = 1.f / l_u, id = 1.f / l_d;
    const int srow = qt * 128 + wid * 16 + grp;
    __half* obase = g_aoh + ((size_t)(b * SEQ + srow)) * HDIM + h * HEADD;
    #pragma unroll
    for (int nt = 0; nt < 8; nt++) {
        int d = nt * 8 + tig * 2;
        *(unsigned*)(obase + d)            = pack2(o[nt][0] * iu, o[nt][1] * iu);
        *(unsigned*)(obase + 8 * HDIM + d) = pack2(o[nt][2] * id, o[nt][3] * id);
    }
}

// ---------------------------------------------------------------------------
extern "C" void kernel_launch(void* const* d_in, const int* in_sizes, int n_in,
                              void* d_out, int out_size)
{
    const float* x  = (const float*)d_in[0];
    const float* Wq = (const float*)d_in[1];
    const float* Wk = (const float*)d_in[2];
    const float* Wv = (const float*)d_in[3];
    const float* Wo = (const float*)d_in[4];
    const float* rc = (const float*)d_in[5];
    const float* rs = (const float*)d_in[6];
    float* out = (float*)d_out;

    cudaFuncSetAttribute(attn_tc,
                         cudaFuncAttributeMaxDynamicSharedMemorySize, ATT_SMEM);
    cudaFuncSetAttribute(gemm_tc,
                         cudaFuncAttributeMaxDynamicSharedMemorySize, GT_SMEM);

    cvt_all<<<4096, 256>>>(x, Wq, Wk, Wv, Wo);

    dim3 ggrid(HDIM / 128, (BATCH * SEQ) / 128);   // (8, 32)
    gemm_tc<<<ggrid, 256, GT_SMEM>>>(nullptr, rc, rs, 1);   // Q (+rope) -> g_qh
    gemm_tc<<<ggrid, 256, GT_SMEM>>>(nullptr, rc, rs, 2);   // K (+rope) -> g_kh
    gemm_tc<<<ggrid, 256, GT_SMEM>>>(nullptr, nullptr, nullptr, 3); // V -> g_vh

    attn_tc<<<dim3(SEQ / 128, BATCH * NHEADS), 256, ATT_SMEM>>>();

    gemm_tc<<<ggrid, 256, GT_SMEM>>>(out, nullptr, nullptr, 0);     // Wo -> out
}

// round 11
// speedup vs baseline: 5.7355x; 1.0433x over previous
#include <cuda_runtime.h>
#include <cuda_fp16.h>
#include <cstdint>

#define HDIM   1024
#define SEQ    2048
#define BATCH  2
#define NHEADS 16
#define HEADD  64

// Scratch (__device__ globals; no allocations allowed)
__device__ __half g_qh [BATCH*NHEADS*SEQ*HEADD];   // fp16 Q (post-rope)
__device__ __half g_kh [BATCH*NHEADS*SEQ*HEADD];   // fp16 K (post-rope)
__device__ __half g_vh [BATCH*NHEADS*SEQ*HEADD];   // fp16 V
__device__ __half g_aoh[BATCH*SEQ*HDIM];           // fp16 attention output
__device__ __half g_xh [BATCH*SEQ*HDIM];           // fp16 x
__device__ __half g_wh [4][HDIM*HDIM];             // fp16 Wq,Wk,Wv,Wo

// ---------------------------------------------------------------- helpers
__device__ __forceinline__ float ex2f(float x) {
    float r; asm("ex2.approx.f32 %0,%1;" : "=f"(r) : "f"(x)); return r;
}
__device__ __forceinline__ unsigned sptr(const void* p) {
    return (unsigned)__cvta_generic_to_shared(p);
}
__device__ __forceinline__ void ldsm4(unsigned a[4], unsigned addr) {
    asm volatile("ldmatrix.sync.aligned.m8n8.x4.shared.b16 {%0,%1,%2,%3}, [%4];"
        : "=r"(a[0]), "=r"(a[1]), "=r"(a[2]), "=r"(a[3]) : "r"(addr));
}
__device__ __forceinline__ void ldsm4t(unsigned a[4], unsigned addr) {
    asm volatile("ldmatrix.sync.aligned.m8n8.x4.trans.shared.b16 {%0,%1,%2,%3}, [%4];"
        : "=r"(a[0]), "=r"(a[1]), "=r"(a[2]), "=r"(a[3]) : "r"(addr));
}
__device__ __forceinline__ void mma16(float c[4], const unsigned a[4],
                                      unsigned b0, unsigned b1) {
    asm volatile(
        "mma.sync.aligned.m16n8k16.row.col.f32.f16.f16.f32 "
        "{%0,%1,%2,%3}, {%4,%5,%6,%7}, {%8,%9}, {%0,%1,%2,%3};\n"
        : "+f"(c[0]), "+f"(c[1]), "+f"(c[2]), "+f"(c[3])
        : "r"(a[0]), "r"(a[1]), "r"(a[2]), "r"(a[3]), "r"(b0), "r"(b1));
}
__device__ __forceinline__ unsigned pack2(float a, float b) {
    __half2 h = __floats2half2_rn(a, b);
    return *reinterpret_cast<unsigned*>(&h);
}
__device__ __forceinline__ uint4 pack8(float4 a, float4 b) {
    uint4 r;
    r.x = pack2(a.x, a.y); r.y = pack2(a.z, a.w);
    r.z = pack2(b.x, b.y); r.w = pack2(b.z, b.w);
    return r;
}
__device__ __forceinline__ void cpa16(unsigned d, const void* s) {
    asm volatile("cp.async.cg.shared.global [%0], [%1], 16;\n" :: "r"(d), "l"(s));
}
__device__ __forceinline__ void cp_commit() {
    asm volatile("cp.async.commit_group;\n");
}
template<int N> __device__ __forceinline__ void cp_wait() {
    asm volatile("cp.async.wait_group %0;\n" :: "n"(N));
}

// ---------------------------------------------------------------------------
// f32 -> fp16 bulk convert, all tensors in ONE launch (uint4 chunks of 8).
// chunks: [0, 512K) = x ; then 4 x 128K = Wq, Wk, Wv, Wo
// ---------------------------------------------------------------------------
__global__ __launch_bounds__(256) void cvt_all(
    const float* __restrict__ x,  const float* __restrict__ wq,
    const float* __restrict__ wk, const float* __restrict__ wv,
    const float* __restrict__ wo)
{
    int i = blockIdx.x * 256 + threadIdx.x;
    const float* src; __half* dst; int base;
    if (i < 524288) { src = x; dst = g_xh; base = i; }
    else {
        int j = i - 524288;
        int w = j >> 17;  base = j & 131071;
        src = (w == 0) ? wq : (w == 1) ? wk : (w == 2) ? wv : wo;
        dst = g_wh[w];
    }
    float4 a = ((const float4*)src)[2*base];
    float4 b = ((const float4*)src)[2*base + 1];
    ((uint4*)dst)[base] = pack8(a, b);
}

// ---------------------------------------------------------------------------
// fp16 mma.sync GEMM, compile-time specialized. C[m,n] = sum_k A[m,k]*W[n,k].
// Block 128x128, 8 warps, warp tile 32(M)x64(N) (full head per warp -> RoPE
// pair (d, d+32) in one thread). K-step 32, 4-stage cp.async, wait_group<2>.
// MODE: 1 -> rope epilogue, blockIdx.z picks (Wq->g_qh | Wk->g_kh)
//       3 -> fp16 scatter g_vh
//       0 -> f32 outF row-major (Wo)
// ---------------------------------------------------------------------------
#define GSTR 40
#define GBUFO (128*GSTR*2)              // bytes per A (or B) stage buffer
#define GT_SMEM (8*GBUFO)               // 4 stages x (A+B) = 81920 B

template<int MODE>
__global__ __launch_bounds__(256) void gemm_k(
    float* __restrict__ outF,
    const float* __restrict__ rc, const float* __restrict__ rs)
{
    extern __shared__ __align__(16) __half gsm[];
    __half* As = gsm;                    // 4 x 128*GSTR
    __half* Bs = gsm + 4*128*GSTR;

    const __half* A = (MODE == 0) ? g_aoh : g_xh;
    const __half* B = (MODE == 0) ? g_wh[3] : (MODE == 3) ? g_wh[2] : g_wh[blockIdx.z];

    const int m0 = blockIdx.y * 128, n0 = blockIdx.x * 128;
    const int t = threadIdx.x, lane = t & 31, wid = t >> 5;
    const int wm = (wid & 3) * 32, wn = (wid >> 2) * 64;

    const int grow = t >> 1;
    const int gcol = (t & 1) * 16;
    const __half* Ag = A + (size_t)(m0 + grow) * HDIM + gcol;
    const __half* Bg = B + (size_t)(n0 + grow) * HDIM + gcol;
    const unsigned aSt = sptr(&As[grow * GSTR + gcol]);
    const unsigned bSt = sptr(&Bs[grow * GSTR + gcol]);

    const int s = lane >> 3, r = lane & 7;
    const unsigned aAddr = sptr(&As[(wm + (s & 1) * 8 + r) * GSTR + (s >> 1) * 8]);
    const unsigned bAddr = sptr(&Bs[(wn + (s & 1) * 8 + r) * GSTR + (s >> 1) * 8]);

    float c[2][8][4];
    #pragma unroll
    for (int i = 0; i < 2; i++)
        #pragma unroll
        for (int j = 0; j < 8; j++)
            #pragma unroll
            for (int q = 0; q < 4; q++) c[i][j][q] = 0.f;

    #define G_LOAD(sl, buf) do { \
        const __half* _as = Ag + (sl) * 32; \
        const __half* _bs = Bg + (sl) * 32; \
        unsigned _o = (buf) * GBUFO; \
        cpa16(aSt + _o,      _as);    cpa16(aSt + _o + 16, _as + 8); \
        cpa16(bSt + _o,      _bs);    cpa16(bSt + _o + 16, _bs + 8); \
        cp_commit(); \
    } while (0)

    G_LOAD(0, 0);
    G_LOAD(1, 1);
    G_LOAD(2, 2);

    const int NIT = HDIM / 32;
    for (int it = 0; it < NIT; it++) {
        const int buf = it & 3;
        cp_wait<2>();
        __syncthreads();
        if (it + 3 < NIT) G_LOAD(it + 3, (it + 3) & 3);
        else              cp_commit();            // keep group count aligned

        const unsigned bo = buf * GBUFO;
        #pragma unroll
        for (int kc = 0; kc < 2; kc++) {
            unsigned aa[2][4], bb[4][4];
            #pragma unroll
            for (int mt = 0; mt < 2; mt++)
                ldsm4(aa[mt], aAddr + bo + mt * (16 * GSTR * 2) + kc * 32);
            #pragma unroll
            for (int p = 0; p < 4; p++)
                ldsm4(bb[p], bAddr + bo + p * (16 * GSTR * 2) + kc * 32);
            #pragma unroll
            for (int mt = 0; mt < 2; mt++)
                #pragma unroll
                for (int nt = 0; nt < 8; nt++)
                    mma16(c[mt][nt], aa[mt],
                          bb[nt >> 1][(nt & 1) ? 1 : 0],
                          bb[nt >> 1][(nt & 1) ? 3 : 2]);
        }
    }
    cp_wait<0>();

    const int grp = lane >> 2, tig = lane & 3;
    if (MODE == 0) {
        #pragma unroll
        for (int mt = 0; mt < 2; mt++)
            #pragma unroll
            for (int nt = 0; nt < 8; nt++) {
                int m = m0 + wm + mt * 16 + grp;
                int n = n0 + wn + nt * 8 + tig * 2;
                *(float2*)(outF + (size_t)m * HDIM + n)       = make_float2(c[mt][nt][0], c[mt][nt][1]);
                *(float2*)(outF + (size_t)(m + 8) * HDIM + n) = make_float2(c[mt][nt][2], c[mt][nt][3]);
            }
    } else if (MODE == 3) {
        const int h = (n0 + wn) >> 6;
        #pragma unroll
        for (int mt = 0; mt < 2; mt++)
            #pragma unroll
            for (int nt = 0; nt < 8; nt++) {
                int m = m0 + wm + mt * 16 + grp;
                int d = nt * 8 + tig * 2;
                int b = m >> 11, sq = m & (SEQ - 1);
                size_t off = (((size_t)(b * NHEADS + h) * SEQ) + sq) * HEADD + d;
                *(unsigned*)(g_vh + off)             = pack2(c[mt][nt][0], c[mt][nt][1]);
                *(unsigned*)(g_vh + off + 8 * HEADD) = pack2(c[mt][nt][2], c[mt][nt][3]);
            }
    } else {
        // RoPE fused: pair (d, d+32) = (c[mt][nt], c[mt][nt+4]), nt < 4.
        __half* dst = blockIdx.z ? g_kh : g_qh;
        const int h = (n0 + wn) >> 6;
        #pragma unroll
        for (int mt = 0; mt < 2; mt++) {
            #pragma unroll
            for (int half = 0; half < 2; half++) {       // rows grp, grp+8
                int m  = m0 + wm + mt * 16 + grp + half * 8;
                int b  = m >> 11, sq = m & (SEQ - 1);
                size_t base = (((size_t)(b * NHEADS + h) * SEQ) + sq) * HEADD;
                const float* rcp = rc + sq * 32;
                const float* rsp = rs + sq * 32;
                const int q0 = half * 2;                 // c idx 0/1 or 2/3
                #pragma unroll
                for (int nt = 0; nt < 4; nt++) {
                    int d0 = nt * 8 + tig * 2;
                    float cc0 = rcp[d0],     ss0 = rsp[d0];
                    float cc1 = rcp[d0 + 1], ss1 = rsp[d0 + 1];
                    float x1a = c[mt][nt][q0],     x2a = c[mt][nt + 4][q0];
                    float x1b = c[mt][nt][q0 + 1], x2b = c[mt][nt + 4][q0 + 1];
                    *(unsigned*)(dst + base + d0) =
                        pack2(x1a * cc0 - x2a * ss0, x1b * cc1 - x2b * ss1);
                    *(unsigned*)(dst + base + d0 + 32) =
                        pack2(x2a * cc0 + x1a * ss0, x2b * cc1 + x1b * ss1);
                }
            }
        }
    }
}

// ---------------------------------------------------------------------------
// Flash attention (unchanged from R10): fp16 smem via 3-deep cp.async KV
// pipeline, ldmatrix.trans for V. Block = (q-tile 128, bh). 2 blocks/SM.
// smem halves (stride 72): Qs[128][72] | Ks[3][64][72] | Vs[3][64][72]
// ---------------------------------------------------------------------------
#define ASTR 72
#define KVH  (64*ASTR)
#define BUFB (KVH*2)
#define ATT_SMEM ((128*ASTR + 6*KVH) * 2)   // 73728 B

__global__ __launch_bounds__(256, 2) void attn_tc()
{
    extern __shared__ __align__(16) __half smh[];
    __half* Qs  = smh;                   // 128*72
    __half* Ks0 = smh + 128*ASTR;        // 3 x 64*72
    __half* Vs0 = Ks0 + 3*KVH;           // 3 x 64*72

    const int bh = blockIdx.y, qt = blockIdx.x;
    const int t = threadIdx.x, lane = t & 31, wid = t >> 5;
    const int s = lane >> 3, r = lane & 7;
    const int grp = lane >> 2, tig = lane & 3;

    const __half* qp    = g_qh + ((size_t)bh * SEQ + qt * 128) * HEADD;
    const __half* kbase = g_kh + (size_t)bh * SEQ * HEADD;
    const __half* vbase = g_vh + (size_t)bh * SEQ * HEADD;

    // ---- prologue: group0 = Q + K0/V0 ; group1 = K1/V1
    {
        const unsigned qDst = sptr(Qs) + ((t >> 1) * ASTR + (t & 1) * 32) * 2;
        const __half* qsrc = qp + (t >> 1) * HEADD + (t & 1) * 32;
        #pragma unroll
        for (int j = 0; j < 4; j++) cpa16(qDst + j * 16, qsrc + j * 8);
    }
    const unsigned kDst = sptr(Ks0) + ((t >> 2) * ASTR + (t & 3) * 16) * 2;
    const unsigned vDst = sptr(Vs0) + ((t >> 2) * ASTR + (t & 3) * 16) * 2;
    const int srcoff = (t >> 2) * HEADD + (t & 3) * 16;
    cpa16(kDst,      kbase + srcoff);     cpa16(kDst + 16, kbase + srcoff + 8);
    cpa16(vDst,      vbase + srcoff);     cpa16(vDst + 16, vbase + srcoff + 8);
    cp_commit();
    {
        const size_t t1 = (size_t)64 * HEADD;
        cpa16(kDst + BUFB,      kbase + t1 + srcoff);
        cpa16(kDst + BUFB + 16, kbase + t1 + srcoff + 8);
        cpa16(vDst + BUFB,      vbase + t1 + srcoff);
        cpa16(vDst + BUFB + 16, vbase + t1 + srcoff + 8);
        cp_commit();
    }

    const unsigned qA = sptr(Qs)  + ((wid * 16 + (s & 1) * 8 + r) * ASTR + (s >> 1) * 8) * 2;
    const unsigned kA = sptr(Ks0) + (((s & 1) * 8 + r) * ASTR + (s >> 1) * 8) * 2;
    const unsigned vA = sptr(Vs0) + (((s & 1) * 8 + r) * ASTR + (s >> 1) * 8) * 2;

    const float SC = 0.125f * 1.4426950408889634f;

    float o[8][4];
    #pragma unroll
    for (int nt = 0; nt < 8; nt++)
        { o[nt][0] = o[nt][1] = o[nt][2] = o[nt][3] = 0.f; }
    float m_u = -1e30f, m_d = -1e30f, l_u = 0.f, l_d = 0.f;

    const int NT = SEQ / 64;
    for (int kt = 0; kt < NT; kt++) {
        const int buf = kt % 3;
        cp_wait<1>();
        __syncthreads();

        // issue tile kt+2 into buffer (kt+2)%3 (clamped; never a live buffer)
        {
            const int kn = (kt + 2 < NT) ? kt + 2 : NT - 1;
            const size_t toff = (size_t)kn * 64 * HEADD;
            const unsigned nb = ((kt + 2) % 3) * BUFB;
            cpa16(kDst + nb,      kbase + toff + srcoff);
            cpa16(kDst + nb + 16, kbase + toff + srcoff + 8);
            cpa16(vDst + nb,      vbase + toff + srcoff);
            cpa16(vDst + nb + 16, vbase + toff + srcoff + 8);
            cp_commit();
        }

        // ---- S = Q K^T (warp: 16 x 64)
        float sc[8][4];
        #pragma unroll
        for (int nt = 0; nt < 8; nt++)
            { sc[nt][0] = sc[nt][1] = sc[nt][2] = sc[nt][3] = 0.f; }
        #pragma unroll
        for (int kc = 0; kc < 4; kc++) {
            unsigned qf[4];
            ldsm4(qf, qA + kc * 32);
            unsigned kb[4][4];
            #pragma unroll
            for (int p = 0; p < 4; p++)
                ldsm4(kb[p], kA + buf * BUFB + p * (16 * ASTR * 2) + kc * 32);
            #pragma unroll
            for (int nt = 0; nt < 8; nt++)
                mma16(sc[nt], qf,
                      kb[nt >> 1][(nt & 1) ? 1 : 0],
                      kb[nt >> 1][(nt & 1) ? 3 : 2]);
        }

        // ---- online softmax (rows grp, grp+8; reduce across 4 lanes)
        float mu = -1e30f, md = -1e30f;
        #pragma unroll
        for (int nt = 0; nt < 8; nt++) {
            mu = fmaxf(mu, fmaxf(sc[nt][0], sc[nt][1]));
            md = fmaxf(md, fmaxf(sc[nt][2], sc[nt][3]));
        }
        mu = fmaxf(mu, __shfl_xor_sync(0xffffffffu, mu, 1));
        mu = fmaxf(mu, __shfl_xor_sync(0xffffffffu, mu, 2));
        md = fmaxf(md, __shfl_xor_sync(0xffffffffu, md, 1));
        md = fmaxf(md, __shfl_xor_sync(0xffffffffu, md, 2));
        float mnu = fmaxf(m_u, mu), mnd = fmaxf(m_d, md);
        float au = ex2f((m_u - mnu) * SC), ad = ex2f((m_d - mnd) * SC);
        m_u = mnu; m_d = mnd;
        const float bu = -mnu * SC, bd = -mnd * SC;

        float su = 0.f, sd = 0.f;
        #pragma unroll
        for (int nt = 0; nt < 8; nt++) {
            sc[nt][0] = ex2f(fmaf(sc[nt][0], SC, bu));
            sc[nt][1] = ex2f(fmaf(sc[nt][1], SC, bu));
            sc[nt][2] = ex2f(fmaf(sc[nt][2], SC, bd));
            sc[nt][3] = ex2f(fmaf(sc[nt][3], SC, bd));
            su += sc[nt][0] + sc[nt][1];
            sd += sc[nt][2] + sc[nt][3];
        }
        su += __shfl_xor_sync(0xffffffffu, su, 1);
        su += __shfl_xor_sync(0xffffffffu, su, 2);
        sd += __shfl_xor_sync(0xffffffffu, sd, 1);
        sd += __shfl_xor_sync(0xffffffffu, sd, 2);
        l_u = l_u * au + su;
        l_d = l_d * ad + sd;
        #pragma unroll
        for (int nt = 0; nt < 8; nt++) {
            o[nt][0] *= au; o[nt][1] *= au;
            o[nt][2] *= ad; o[nt][3] *= ad;
        }

        // ---- O += P V : A-frags = repacked S; B-frags via ldmatrix.trans
        #pragma unroll
        for (int kc = 0; kc < 4; kc++) {
            unsigned af[4];
            af[0] = pack2(sc[2*kc][0],   sc[2*kc][1]);
            af[1] = pack2(sc[2*kc][2],   sc[2*kc][3]);
            af[2] = pack2(sc[2*kc+1][0], sc[2*kc+1][1]);
            af[3] = pack2(sc[2*kc+1][2], sc[2*kc+1][3]);
            #pragma unroll
            for (int p = 0; p < 4; p++) {
                unsigned vb[4];
                ldsm4t(vb, vA + buf * BUFB + kc * (16 * ASTR * 2) + p * 32);
                mma16(o[2*p],   af, vb[0], vb[1]);
                mma16(o[2*p+1], af, vb[2], vb[3]);
            }
        }
    }
    cp_wait<0>();

    // ---- epilogue: normalize, write fp16 g_aoh [B,S,H]
    const int b = bh >> 4, h = bh & 15;
    const float iu = 1.f / l_u, id = 1.f / l_d;
    const int srow = qt * 128 + wid * 16 + grp;
    __half* obase = g_aoh + ((size_t)(b * SEQ + srow)) * HDIM + h * HEADD;
    #pragma unroll
    for (int nt = 0; nt < 8; nt++) {
        int d = nt * 8 + tig * 2;
        *(unsigned*)(obase + d)            = pack2(o[nt][0] * iu, o[nt][1] * iu);
        *(unsigned*)(obase + 8 * HDIM + d) = pack2(o[nt][2] * id, o[nt][3] * id);
    }
}

// ---------------------------------------------------------------------------
extern "C" void kernel_launch(void* const* d_in, const int* in_sizes, int n_in,
                              void* d_out, int out_size)
{
    const float* x  = (const float*)d_in[0];
    const float* Wq = (const float*)d_in[1];
    const float* Wk = (const float*)d_in[2];
    const float* Wv = (const float*)d_in[3];
    const float* Wv_ = (const float*)d_in[3];
    const float* Wo = (const float*)d_in[4];
    const float* rc = (const float*)d_in[5];
    const float* rs = (const float*)d_in[6];
    float* out = (float*)d_out;
    (void)Wv_;

    cudaFuncSetAttribute(attn_tc,
                         cudaFuncAttributeMaxDynamicSharedMemorySize, ATT_SMEM);
    cudaFuncSetAttribute(gemm_k<0>,
                         cudaFuncAttributeMaxDynamicSharedMemorySize, GT_SMEM);
    cudaFuncSetAttribute(gemm_k<1>,
                         cudaFuncAttributeMaxDynamicSharedMemorySize, GT_SMEM);
    cudaFuncSetAttribute(gemm_k<3>,
                         cudaFuncAttributeMaxDynamicSharedMemorySize, GT_SMEM);

    cvt_all<<<4096, 256>>>(x, Wq, Wk, Wv, Wo);

    dim3 gQK(HDIM / 128, (BATCH * SEQ) / 128, 2);   // (8, 32, 2) = 512 CTAs
    dim3 g1 (HDIM / 128, (BATCH * SEQ) / 128, 1);   // (8, 32)    = 256 CTAs
    gemm_k<1><<<gQK, 256, GT_SMEM>>>(nullptr, rc, rs);   // Q+K (+rope)
    gemm_k<3><<<g1,  256, GT_SMEM>>>(nullptr, nullptr, nullptr); // V -> g_vh

    attn_tc<<<dim3(SEQ / 128, BATCH * NHEADS), 256, ATT_SMEM>>>();

    gemm_k<0><<<g1,  256, GT_SMEM>>>(out, nullptr, nullptr);     // Wo -> out
}